// round 8
// baseline (speedup 1.0000x reference)
#include <cuda_runtime.h>
#include <cstddef>
#include <cstdint>

#define Bc 48
#define Wn 8192
#define Fc 64
#define Dc 128
#define GRAM_CHUNKS 32

typedef unsigned long long ull;

// device scratch (no runtime allocation allowed)
__device__ float g_gram_part[Bc * GRAM_CHUNKS * Fc * Fc];
__device__ float g_gram[Bc * Fc * Fc];
__device__ float g_h[(size_t)Bc * Wn * Fc];     // 100.7 MB intermediate
__device__ float g_cwB[64 * 192];               // ctx_w reordered   [f][k*64+g]
__device__ float g_twB[128 * 192];              // token_w reordered [d][k*64+f]

// ---------------------------------------------------------------------------
// packed f32x2 helpers (still used by gram)
// ---------------------------------------------------------------------------
__device__ __forceinline__ ull dup2(float a) {
    ull r;
    asm("mov.b64 %0, {%1, %1};" : "=l"(r) : "r"(__float_as_uint(a)));
    return r;
}
__device__ __forceinline__ void unpack2(ull v, float& a, float& b) {
    unsigned lo, hi;
    asm("mov.b64 {%0, %1}, %2;" : "=r"(lo), "=r"(hi) : "l"(v));
    a = __uint_as_float(lo); b = __uint_as_float(hi);
}
__device__ __forceinline__ ull ffma2(ull a, ull b, ull c) {
    ull d;
    asm("fma.rn.f32x2 %0, %1, %2, %3;" : "=l"(d) : "l"(a), "l"(b), "l"(c));
    return d;
}

// ---------------------------------------------------------------------------
// tensor-core helpers (legacy mma.sync path — compiles under compute_103)
// ---------------------------------------------------------------------------
__device__ __forceinline__ uint32_t smem_u32(const void* p) {
    uint32_t a;
    asm("{ .reg .u64 t; cvta.to.shared.u64 t, %1; cvt.u32.u64 %0, t; }" : "=r"(a) : "l"(p));
    return a;
}
__device__ __forceinline__ uint32_t cvt_tf32(float x) {
    uint32_t r;
    asm("cvt.rna.tf32.f32 %0, %1;" : "=r"(r) : "f"(x));
    return r;
}
__device__ __forceinline__ void ldsm_x4(uint32_t addr, uint32_t* r) {
    asm volatile("ldmatrix.sync.aligned.m8n8.x4.shared.b16 {%0,%1,%2,%3}, [%4];"
                 : "=r"(r[0]), "=r"(r[1]), "=r"(r[2]), "=r"(r[3]) : "r"(addr));
}
__device__ __forceinline__ void mma_tf32(float* c, const uint32_t* a,
                                         uint32_t b0, uint32_t b1) {
    asm volatile(
        "mma.sync.aligned.m16n8k8.row.col.f32.tf32.tf32.f32 "
        "{%0,%1,%2,%3}, {%4,%5,%6,%7}, {%8,%9}, {%0,%1,%2,%3};"
        : "+f"(c[0]), "+f"(c[1]), "+f"(c[2]), "+f"(c[3])
        : "r"(a[0]), "r"(a[1]), "r"(a[2]), "r"(a[3]), "r"(b0), "r"(b1));
}

// ---------------------------------------------------------------------------
// Kernel 0: one-time weight reorders (tiny)
// ---------------------------------------------------------------------------
__global__ void __launch_bounds__(256) transpose_weights(
    const float* __restrict__ ctx_w, const float* __restrict__ token_w) {
    int tid = blockIdx.x * 256 + threadIdx.x;
    int nt = gridDim.x * 256;
    // g_cwB[f][k*64+g] = ctx_w[f][g*3+k]
    for (int i = tid; i < 64 * 192; i += nt) {
        int f = i / 192, j = i - f * 192;
        int k = j >> 6, g = j & 63;
        g_cwB[i] = ctx_w[f * 192 + g * 3 + k];
    }
    // g_twB[d][k*64+f] = token_w[d][f*3+k]
    for (int i = tid; i < 128 * 192; i += nt) {
        int d = i / 192, j = i - d * 192;
        int k = j >> 6, f = j & 63;
        g_twB[i] = token_w[d * 192 + f * 3 + k];
    }
}

// ---------------------------------------------------------------------------
// Kernel 1: per-chunk partial Gram (FFMA2, parallel norm). Unchanged.
// ---------------------------------------------------------------------------
__global__ void __launch_bounds__(256) gram_partial(const float* __restrict__ x) {
    const int b = blockIdx.y;
    const int chunk = blockIdx.x;
    const int w_base = chunk * (Wn / GRAM_CHUNKS);

    __shared__ float xs[64][66];
    __shared__ float npart[4][64];
    __shared__ float sinv2[64];

    const int t = threadIdx.x;
    const int ti = t >> 4;
    const int tj = t & 15;

    ull acc[4][2];
    #pragma unroll
    for (int a = 0; a < 4; a++) { acc[a][0] = 0ull; acc[a][1] = 0ull; }

    const float* xb = x + (size_t)b * Wn * Fc;

    for (int tile = 0; tile < 256; tile += 64) {
        for (int i = t; i < 64 * 64; i += 256) {
            int r = i >> 6, c = i & 63;
            xs[r][c] = xb[(size_t)(w_base + tile + r) * Fc + c];
        }
        __syncthreads();
        {
            int q = t >> 6, r = t & 63;
            float s = 0.f;
            #pragma unroll
            for (int c = 0; c < 16; c++) { float v = xs[r][q * 16 + c]; s += v * v; }
            npart[q][r] = s;
        }
        __syncthreads();
        if (t < 64)
            sinv2[t] = 1.0f / (npart[0][t] + npart[1][t] + npart[2][t] + npart[3][t]);
        __syncthreads();

        #pragma unroll 4
        for (int w = 0; w < 64; w++) {
            float s = sinv2[w];
            const ull* row = (const ull*)(&xs[w][0]);
            ull vj0 = row[tj], vj1 = row[tj + 16];
            float vi0 = xs[w][ti] * s,      vi1 = xs[w][ti + 16] * s;
            float vi2 = xs[w][ti + 32] * s, vi3 = xs[w][ti + 48] * s;
            acc[0][0] = ffma2(dup2(vi0), vj0, acc[0][0]);
            acc[0][1] = ffma2(dup2(vi0), vj1, acc[0][1]);
            acc[1][0] = ffma2(dup2(vi1), vj0, acc[1][0]);
            acc[1][1] = ffma2(dup2(vi1), vj1, acc[1][1]);
            acc[2][0] = ffma2(dup2(vi2), vj0, acc[2][0]);
            acc[2][1] = ffma2(dup2(vi2), vj1, acc[2][1]);
            acc[3][0] = ffma2(dup2(vi3), vj0, acc[3][0]);
            acc[3][1] = ffma2(dup2(vi3), vj1, acc[3][1]);
        }
        __syncthreads();
    }

    float* dst = g_gram_part + ((size_t)b * GRAM_CHUNKS + chunk) * (Fc * Fc);
    #pragma unroll
    for (int a = 0; a < 4; a++)
        #pragma unroll
        for (int c = 0; c < 2; c++) {
            float u, v;
            unpack2(acc[a][c], u, v);
            *(float2*)(dst + (ti + 16 * a) * 64 + 2 * (tj + 16 * c)) = make_float2(u, v);
        }
}

__global__ void __launch_bounds__(256) gram_reduce() {
    const int b = blockIdx.x;
    const int t = threadIdx.x;
    for (int i = t; i < Fc * Fc; i += 256) {
        float s = 0.f;
        #pragma unroll
        for (int c = 0; c < GRAM_CHUNKS; c++)
            s += g_gram_part[((size_t)b * GRAM_CHUNKS + c) * (Fc * Fc) + i];
        g_gram[b * Fc * Fc + i] = s;
    }
}

// ---------------------------------------------------------------------------
// Kernel H (mma.sync tf32): h[128w x 64f tile] per CTA.
//   SE  : A = seW rows [128][64], B = gram [64][64]          (K=64)
//   conv: A = x rows [130][64] zero-pad, B = g_cwB [64][192] (3 passes x K=64)
//   h = conv + ctx_b + relu(SE + seb)
// 16 warps: warp tile 32w x 16f (2 m-tiles x 2 n-tiles).
// ---------------------------------------------------------------------------
#define HM_AX   0                         // 130*272 = 35360 B (stride 68 words)
#define HM_AS   35360                     // 128*272 = 34816 B
#define HM_BC   70176                     // 64*784  = 50176 B (stride 196 words)
#define HM_BG   120352                    // 64*272  = 17408 B
#define HM_SMEM 137760

__global__ void __launch_bounds__(512, 1) h_mma_kernel(
    const float* __restrict__ x,
    const float* __restrict__ ctx_b,
    const float* __restrict__ seW_w,
    const float* __restrict__ seW_b)
{
    extern __shared__ char smc[];
    uint32_t sbase = smem_u32(smc);
    const int t   = threadIdx.x;
    const int wid = t >> 5;
    const int l   = t & 31;
    const int b   = blockIdx.y;
    const int w0  = blockIdx.x * 128;

    // ---- staging ----
    const float* xb = x + (size_t)b * Wn * Fc;
    for (int i = t; i < 130 * 64; i += 512) {
        int j = i >> 6, f = i & 63;
        int gr = w0 - 1 + j;
        float v = (gr >= 0 && gr < Wn) ? xb[(size_t)gr * Fc + f] : 0.f;
        *(uint32_t*)(smc + HM_AX + (j * 68 + f) * 4) = cvt_tf32(v);
    }
    for (int i = t; i < 128 * 64; i += 512) {
        int r = i >> 6, g = i & 63;
        *(uint32_t*)(smc + HM_AS + (r * 68 + g) * 4) =
            cvt_tf32(seW_w[(size_t)(w0 + r) * Fc + g]);
    }
    for (int i = t; i < 64 * 192; i += 512) {
        int f = i / 192, kk = i - f * 192;
        *(uint32_t*)(smc + HM_BC + (f * 196 + kk) * 4) = cvt_tf32(g_cwB[i]);
    }
    for (int i = t; i < 64 * 64; i += 512) {
        int f = i >> 6, g = i & 63;
        *(uint32_t*)(smc + HM_BG + (f * 68 + g) * 4) = cvt_tf32(g_gram[b * 4096 + i]);
    }
    __syncthreads();

    const int R  = (wid & 3) * 32;         // warp w-base
    const int Fo = (wid >> 2) * 16;        // warp f-base

    // per-lane ldmatrix addresses
    const int a_row_in = (l & 7) + ((l >> 3) & 1) * 8;
    const uint32_t a_col = (uint32_t)(l >> 4) * 16;
    uint32_t aAX = sbase + HM_AX + (uint32_t)(R + a_row_in) * 272 + a_col;
    uint32_t aAS = sbase + HM_AS + (uint32_t)(R + a_row_in) * 272 + a_col;
    const int b_row_in = (l & 7) + (l >> 4) * 8;
    const uint32_t b_col = (uint32_t)((l >> 3) & 1) * 16;
    uint32_t aBC = sbase + HM_BC + (uint32_t)(Fo + b_row_in) * 784 + b_col;
    uint32_t aBG = sbase + HM_BG + (uint32_t)(Fo + b_row_in) * 272 + b_col;

    float acc_cv[4][4], acc_se[4][4];
    #pragma unroll
    for (int i = 0; i < 4; i++)
        #pragma unroll
        for (int j = 0; j < 4; j++) { acc_cv[i][j] = 0.f; acc_se[i][j] = 0.f; }

    // ---- SE GEMM: K=64 ----
    #pragma unroll
    for (int s = 0; s < 8; s++) {
        uint32_t fa0[4], fa1[4], fb[4];
        ldsm_x4(aAS + 32u * s, fa0);
        ldsm_x4(aAS + 16u * 272 + 32u * s, fa1);
        ldsm_x4(aBG + 32u * s, fb);
        mma_tf32(acc_se[0], fa0, fb[0], fb[1]);   // mt0, nt0
        mma_tf32(acc_se[1], fa0, fb[2], fb[3]);   // mt0, nt1
        mma_tf32(acc_se[2], fa1, fb[0], fb[1]);   // mt1, nt0
        mma_tf32(acc_se[3], fa1, fb[2], fb[3]);   // mt1, nt1
    }

    // ---- conv GEMM: 3 passes (tap = A row shift) x K=64 ----
    #pragma unroll
    for (int pass = 0; pass < 3; pass++) {
        uint32_t abase = aAX + (uint32_t)pass * 272;
        uint32_t bbase = aBC + (uint32_t)pass * 256;
        #pragma unroll
        for (int s = 0; s < 8; s++) {
            uint32_t fa0[4], fa1[4], fb[4];
            ldsm_x4(abase + 32u * s, fa0);
            ldsm_x4(abase + 16u * 272 + 32u * s, fa1);
            ldsm_x4(bbase + 32u * s, fb);
            mma_tf32(acc_cv[0], fa0, fb[0], fb[1]);
            mma_tf32(acc_cv[1], fa0, fb[2], fb[3]);
            mma_tf32(acc_cv[2], fa1, fb[0], fb[1]);
            mma_tf32(acc_cv[3], fa1, fb[2], fb[3]);
        }
    }

    // ---- epilogue: h = conv + ctx_b + relu(SE + seb) ----
    const int gr  = l >> 2;
    const int gc2 = (l & 3) * 2;
    #pragma unroll
    for (int mt = 0; mt < 2; mt++) {
        int row0 = w0 + R + mt * 16 + gr;
        float seb0 = __ldg(seW_b + row0);
        float seb1 = __ldg(seW_b + row0 + 8);
        #pragma unroll
        for (int nt = 0; nt < 2; nt++) {
            const float* cv = acc_cv[mt * 2 + nt];
            const float* se = acc_se[mt * 2 + nt];
            int col = Fo + nt * 8 + gc2;
            float cb0 = __ldg(ctx_b + col), cb1 = __ldg(ctx_b + col + 1);
            float* h0 = g_h + ((size_t)b * Wn + row0) * Fc + col;
            *(float2*)(h0) = make_float2(cv[0] + cb0 + fmaxf(se[0] + seb0, 0.f),
                                         cv[1] + cb1 + fmaxf(se[1] + seb0, 0.f));
            *(float2*)(h0 + 8 * Fc) = make_float2(cv[2] + cb0 + fmaxf(se[2] + seb1, 0.f),
                                                  cv[3] + cb1 + fmaxf(se[3] + seb1, 0.f));
        }
    }
}

// ---------------------------------------------------------------------------
// Kernel O (mma.sync tf32): unchanged R7 winner.
// ---------------------------------------------------------------------------
#define OM_A     0
#define OM_ASTR  68
#define OM_B     (130 * 272)              // 35360 B
#define OM_BSTR  196
#define OM_SMEM  (OM_B + 128 * 784)       // 135712 B

__global__ void __launch_bounds__(512, 1) out_mma_kernel(float* __restrict__ out)
{
    extern __shared__ char smc[];
    uint32_t sbase = smem_u32(smc);
    const int t   = threadIdx.x;
    const int wid = t >> 5;
    const int l   = t & 31;
    const int b   = blockIdx.y;
    const int w0  = blockIdx.x * 128;

    const float* hb = g_h + (size_t)b * Wn * Fc;
    for (int i = t; i < 130 * 64; i += 512) {
        int j = i >> 6, f = i & 63;
        int gw = (w0 - 1 + j + Wn) & (Wn - 1);
        *(uint32_t*)(smc + OM_A + (j * OM_ASTR + f) * 4) = cvt_tf32(hb[(size_t)gw * Fc + f]);
    }
    for (int i = t; i < 128 * 192; i += 512) {
        int d = i / 192, kk = i - d * 192;
        *(uint32_t*)(smc + OM_B + (d * OM_BSTR + kk) * 4) = cvt_tf32(g_twB[i]);
    }
    __syncthreads();

    const int R = (wid & 3) * 32;
    const int D = (wid >> 2) * 32;

    const int a_row_in = (l & 7) + ((l >> 3) & 1) * 8;
    uint32_t aA = sbase + OM_A + (uint32_t)(R + a_row_in) * 272 + (uint32_t)(l >> 4) * 16;
    const int b_d_in = (l & 7) + (l >> 4) * 8;
    uint32_t aB = sbase + OM_B + (uint32_t)(D + b_d_in) * 784 + (uint32_t)((l >> 3) & 1) * 16;

    float acc[8][4];
    #pragma unroll
    for (int i = 0; i < 8; i++)
        #pragma unroll
        for (int j = 0; j < 4; j++) acc[i][j] = 0.f;

    #pragma unroll
    for (int pass = 0; pass < 3; pass++) {
        uint32_t a0base = aA + (uint32_t)pass * 272;
        uint32_t b0base = aB + (uint32_t)pass * 256;
        #pragma unroll
        for (int s = 0; s < 8; s++) {
            uint32_t fa0[4], fa1[4], fb0[4], fb1[4];
            ldsm_x4(a0base + 32u * s, fa0);
            ldsm_x4(a0base + 16u * 272 + 32u * s, fa1);
            ldsm_x4(b0base + 32u * s, fb0);
            ldsm_x4(b0base + 16u * 784 + 32u * s, fb1);
            mma_tf32(acc[0], fa0, fb0[0], fb0[1]);
            mma_tf32(acc[1], fa0, fb0[2], fb0[3]);
            mma_tf32(acc[2], fa0, fb1[0], fb1[1]);
            mma_tf32(acc[3], fa0, fb1[2], fb1[3]);
            mma_tf32(acc[4], fa1, fb0[0], fb0[1]);
            mma_tf32(acc[5], fa1, fb0[2], fb0[3]);
            mma_tf32(acc[6], fa1, fb1[0], fb1[1]);
            mma_tf32(acc[7], fa1, fb1[2], fb1[3]);
        }
    }

    const int gr  = l >> 2;
    const int gc2 = (l & 3) * 2;
    #pragma unroll
    for (int mt = 0; mt < 2; mt++) {
        #pragma unroll
        for (int nt = 0; nt < 4; nt++) {
            const float* c = acc[mt * 4 + nt];
            int w_row = w0 + R + mt * 16 + gr;
            int d_col = D + nt * 8 + gc2;
            float* ob = out + ((size_t)b * Wn + w_row) * Dc + d_col;
            *(float2*)(ob)          = make_float2(c[0], c[1]);
            *(float2*)(ob + 8 * Dc) = make_float2(c[2], c[3]);
        }
    }
}

// ---------------------------------------------------------------------------
extern "C" void kernel_launch(void* const* d_in, const int* in_sizes, int n_in,
                              void* d_out, int out_size) {
    const float* x       = (const float*)d_in[0];
    const float* ctx_w   = (const float*)d_in[1];
    const float* ctx_b   = (const float*)d_in[2];
    const float* token_w = (const float*)d_in[3];
    const float* seW_w   = (const float*)d_in[4];
    const float* seW_b   = (const float*)d_in[5];
    float* out = (float*)d_out;

    cudaFuncSetAttribute(h_mma_kernel,
                         cudaFuncAttributeMaxDynamicSharedMemorySize, HM_SMEM);
    cudaFuncSetAttribute(out_mma_kernel,
                         cudaFuncAttributeMaxDynamicSharedMemorySize, OM_SMEM);

    transpose_weights<<<48, 256>>>(ctx_w, token_w);
    gram_partial<<<dim3(GRAM_CHUNKS, Bc), 256>>>(x);
    gram_reduce<<<Bc, 256>>>();
    h_mma_kernel<<<dim3(Wn / 128, Bc), 512, HM_SMEM>>>(x, ctx_b, seW_w, seW_b);
    out_mma_kernel<<<dim3(Wn / 128, Bc), 512, OM_SMEM>>>(out);
}

// round 9
// speedup vs baseline: 1.9025x; 1.9025x over previous
#include <cuda_runtime.h>
#include <cstddef>
#include <cstdint>

#define Bc 48
#define Wn 8192
#define Fc 64
#define Dc 128
#define GRAM_CHUNKS 32

typedef unsigned long long ull;

// device scratch (no runtime allocation allowed). 16B-aligned for vector/cp.async.
__device__ __align__(16) float g_gram_part[Bc * GRAM_CHUNKS * Fc * Fc];
__device__ __align__(16) float g_gram[Bc * Fc * Fc];          // tf32-rounded bits
__device__ __align__(16) float g_h[(size_t)Bc * Wn * Fc];     // tf32-rounded bits
__device__ __align__(16) float g_cwB[64 * 192];               // [f][k*64+g], tf32 bits
__device__ __align__(16) float g_twB[128 * 192];              // [d][k*64+f], tf32 bits
__device__ __align__(16) float g_sewr[Wn * Fc];               // seW rounded tf32 bits

// ---------------------------------------------------------------------------
// packed f32x2 helpers (gram)
// ---------------------------------------------------------------------------
__device__ __forceinline__ ull dup2(float a) {
    ull r;
    asm("mov.b64 %0, {%1, %1};" : "=l"(r) : "r"(__float_as_uint(a)));
    return r;
}
__device__ __forceinline__ void unpack2(ull v, float& a, float& b) {
    unsigned lo, hi;
    asm("mov.b64 {%0, %1}, %2;" : "=r"(lo), "=r"(hi) : "l"(v));
    a = __uint_as_float(lo); b = __uint_as_float(hi);
}
__device__ __forceinline__ ull ffma2(ull a, ull b, ull c) {
    ull d;
    asm("fma.rn.f32x2 %0, %1, %2, %3;" : "=l"(d) : "l"(a), "l"(b), "l"(c));
    return d;
}

// ---------------------------------------------------------------------------
// tensor-core / async helpers (legacy paths — compile under compute_103)
// ---------------------------------------------------------------------------
__device__ __forceinline__ uint32_t smem_u32(const void* p) {
    uint32_t a;
    asm("{ .reg .u64 t; cvta.to.shared.u64 t, %1; cvt.u32.u64 %0, t; }" : "=r"(a) : "l"(p));
    return a;
}
__device__ __forceinline__ uint32_t cvt_tf32(float x) {
    uint32_t r;
    asm("cvt.rna.tf32.f32 %0, %1;" : "=r"(r) : "f"(x));
    return r;
}
__device__ __forceinline__ void cp_async16(uint32_t saddr, const void* gptr) {
    asm volatile("cp.async.ca.shared.global [%0], [%1], 16;" :: "r"(saddr), "l"(gptr));
}
__device__ __forceinline__ void cp_async_wait_all() {
    asm volatile("cp.async.commit_group;");
    asm volatile("cp.async.wait_group 0;" ::: "memory");
}
__device__ __forceinline__ void ldsm_x4(uint32_t addr, uint32_t* r) {
    asm volatile("ldmatrix.sync.aligned.m8n8.x4.shared.b16 {%0,%1,%2,%3}, [%4];"
                 : "=r"(r[0]), "=r"(r[1]), "=r"(r[2]), "=r"(r[3]) : "r"(addr));
}
__device__ __forceinline__ void mma_tf32(float* c, const uint32_t* a,
                                         uint32_t b0, uint32_t b1) {
    asm volatile(
        "mma.sync.aligned.m16n8k8.row.col.f32.tf32.tf32.f32 "
        "{%0,%1,%2,%3}, {%4,%5,%6,%7}, {%8,%9}, {%0,%1,%2,%3};"
        : "+f"(c[0]), "+f"(c[1]), "+f"(c[2]), "+f"(c[3])
        : "r"(a[0]), "r"(a[1]), "r"(a[2]), "r"(a[3]), "r"(b0), "r"(b1));
}

// ---------------------------------------------------------------------------
// Kernel 0: weight reorders + pre-rounding (tiny)
// ---------------------------------------------------------------------------
__global__ void __launch_bounds__(256) transpose_weights(
    const float* __restrict__ ctx_w, const float* __restrict__ token_w,
    const float* __restrict__ seW_w) {
    int tid = blockIdx.x * 256 + threadIdx.x;
    int nt = gridDim.x * 256;
    // g_cwB[f][k*64+g] = rnd(ctx_w[f][g*3+k])
    for (int i = tid; i < 64 * 192; i += nt) {
        int f = i / 192, j = i - f * 192;
        int k = j >> 6, g = j & 63;
        g_cwB[i] = __uint_as_float(cvt_tf32(ctx_w[f * 192 + g * 3 + k]));
    }
    // g_twB[d][k*64+f] = rnd(token_w[d][f*3+k])
    for (int i = tid; i < 128 * 192; i += nt) {
        int d = i / 192, j = i - d * 192;
        int k = j >> 6, f = j & 63;
        g_twB[i] = __uint_as_float(cvt_tf32(token_w[d * 192 + f * 3 + k]));
    }
    // g_sewr = rnd(seW_w), float4
    for (int i = tid; i < Wn * Fc / 4; i += nt) {
        float4 v = *((const float4*)seW_w + i);
        uint4 u = make_uint4(cvt_tf32(v.x), cvt_tf32(v.y), cvt_tf32(v.z), cvt_tf32(v.w));
        *((uint4*)g_sewr + i) = u;
    }
}

// ---------------------------------------------------------------------------
// Kernel 1: per-chunk partial Gram (FFMA2, float4 loads, parallel norm).
// ---------------------------------------------------------------------------
__global__ void __launch_bounds__(256) gram_partial(const float* __restrict__ x) {
    const int b = blockIdx.y;
    const int chunk = blockIdx.x;
    const int w_base = chunk * (Wn / GRAM_CHUNKS);

    __shared__ float xs[64][68];
    __shared__ float npart[4][64];
    __shared__ float sinv2[64];

    const int t = threadIdx.x;
    const int ti = t >> 4;
    const int tj = t & 15;

    ull acc[4][2];
    #pragma unroll
    for (int a = 0; a < 4; a++) { acc[a][0] = 0ull; acc[a][1] = 0ull; }

    const float* xb = x + (size_t)b * Wn * Fc;

    for (int tile = 0; tile < 256; tile += 64) {
        // float4 loads: 1024 chunks
        for (int i = t; i < 64 * 16; i += 256) {
            int r = i >> 4, c4 = i & 15;
            float4 v = *(const float4*)(xb + (size_t)(w_base + tile + r) * Fc + c4 * 4);
            *(float4*)(&xs[r][c4 * 4]) = v;
        }
        __syncthreads();
        {
            int q = t >> 6, r = t & 63;
            float s = 0.f;
            #pragma unroll
            for (int c = 0; c < 16; c++) { float v = xs[r][q * 16 + c]; s += v * v; }
            npart[q][r] = s;
        }
        __syncthreads();
        if (t < 64)
            sinv2[t] = 1.0f / (npart[0][t] + npart[1][t] + npart[2][t] + npart[3][t]);
        __syncthreads();

        #pragma unroll 4
        for (int w = 0; w < 64; w++) {
            float s = sinv2[w];
            const ull* row = (const ull*)(&xs[w][0]);
            ull vj0 = row[tj], vj1 = row[tj + 16];
            float vi0 = xs[w][ti] * s,      vi1 = xs[w][ti + 16] * s;
            float vi2 = xs[w][ti + 32] * s, vi3 = xs[w][ti + 48] * s;
            acc[0][0] = ffma2(dup2(vi0), vj0, acc[0][0]);
            acc[0][1] = ffma2(dup2(vi0), vj1, acc[0][1]);
            acc[1][0] = ffma2(dup2(vi1), vj0, acc[1][0]);
            acc[1][1] = ffma2(dup2(vi1), vj1, acc[1][1]);
            acc[2][0] = ffma2(dup2(vi2), vj0, acc[2][0]);
            acc[2][1] = ffma2(dup2(vi2), vj1, acc[2][1]);
            acc[3][0] = ffma2(dup2(vi3), vj0, acc[3][0]);
            acc[3][1] = ffma2(dup2(vi3), vj1, acc[3][1]);
        }
        __syncthreads();
    }

    float* dst = g_gram_part + ((size_t)b * GRAM_CHUNKS + chunk) * (Fc * Fc);
    #pragma unroll
    for (int a = 0; a < 4; a++)
        #pragma unroll
        for (int c = 0; c < 2; c++) {
            float u, v;
            unpack2(acc[a][c], u, v);
            *(float2*)(dst + (ti + 16 * a) * 64 + 2 * (tj + 16 * c)) = make_float2(u, v);
        }
}

// reduce partials, round to tf32 bits
__global__ void __launch_bounds__(256) gram_reduce() {
    const int b = blockIdx.x;
    const int t = threadIdx.x;
    for (int i = t; i < Fc * Fc; i += 256) {
        float s = 0.f;
        #pragma unroll
        for (int c = 0; c < GRAM_CHUNKS; c++)
            s += g_gram_part[((size_t)b * GRAM_CHUNKS + c) * (Fc * Fc) + i];
        g_gram[b * Fc * Fc + i] = __uint_as_float(cvt_tf32(s));
    }
}

// ---------------------------------------------------------------------------
// Kernel H (mma.sync tf32): h[128w x 64f tile] per CTA.
//   SE  : A = seW rows [128][64], B = gram [64][64]          (K=64)
//   conv: A = x rows [130][64] zero-pad, B = g_cwB [64][192] (3 passes x K=64)
//   h = conv + ctx_b + relu(SE + seb), stored tf32-rounded.
// ---------------------------------------------------------------------------
#define HM_AX   0                         // 130*272 B (stride 68 words)
#define HM_AS   35360                     // 128*272 B
#define HM_BC   70176                     // 64*784 B (stride 196 words)
#define HM_BG   120352                    // 64*272 B
#define HM_SMEM 137760

__global__ void __launch_bounds__(512, 1) h_mma_kernel(
    const float* __restrict__ x,
    const float* __restrict__ ctx_b,
    const float* __restrict__ seW_b)
{
    extern __shared__ char smc[];
    uint32_t sbase = smem_u32(smc);
    const int t   = threadIdx.x;
    const int wid = t >> 5;
    const int l   = t & 31;
    const int b   = blockIdx.y;
    const int w0  = blockIdx.x * 128;

    // ---- staging: cp.async for pre-rounded operands ----
    for (int i = t; i < 128 * 16; i += 512) {            // seW: 2048 chunks
        int r = i >> 4, c4 = i & 15;
        cp_async16(sbase + HM_AS + r * 272 + c4 * 16,
                   g_sewr + (size_t)(w0 + r) * Fc + c4 * 4);
    }
    for (int i = t; i < 64 * 48; i += 512) {             // BC: 3072 chunks
        int f = i / 48, c4 = i - f * 48;
        cp_async16(sbase + HM_BC + f * 784 + c4 * 16, g_cwB + f * 192 + c4 * 4);
    }
    for (int i = t; i < 64 * 16; i += 512) {             // BG: 1024 chunks
        int f = i >> 4, c4 = i & 15;
        cp_async16(sbase + HM_BG + f * 272 + c4 * 16, g_gram + b * 4096 + f * 64 + c4 * 4);
    }
    // x: float4 LDG + cvt + STS.128 (only cvt-on-path left)
    const float* xb = x + (size_t)b * Wn * Fc;
    for (int i = t; i < 130 * 16; i += 512) {
        int j = i >> 4, c4 = i & 15;
        int gr = w0 - 1 + j;
        float4 v = (gr >= 0 && gr < Wn)
                       ? *(const float4*)(xb + (size_t)gr * Fc + c4 * 4)
                       : make_float4(0.f, 0.f, 0.f, 0.f);
        uint4 u = make_uint4(cvt_tf32(v.x), cvt_tf32(v.y), cvt_tf32(v.z), cvt_tf32(v.w));
        *(uint4*)(smc + HM_AX + j * 272 + c4 * 16) = u;
    }
    cp_async_wait_all();
    __syncthreads();

    const int R  = (wid & 3) * 32;         // warp w-base
    const int Fo = (wid >> 2) * 16;        // warp f-base

    const int a_row_in = (l & 7) + ((l >> 3) & 1) * 8;
    const uint32_t a_col = (uint32_t)(l >> 4) * 16;
    uint32_t aAX = sbase + HM_AX + (uint32_t)(R + a_row_in) * 272 + a_col;
    uint32_t aAS = sbase + HM_AS + (uint32_t)(R + a_row_in) * 272 + a_col;
    const int b_row_in = (l & 7) + (l >> 4) * 8;
    const uint32_t b_col = (uint32_t)((l >> 3) & 1) * 16;
    uint32_t aBC = sbase + HM_BC + (uint32_t)(Fo + b_row_in) * 784 + b_col;
    uint32_t aBG = sbase + HM_BG + (uint32_t)(Fo + b_row_in) * 272 + b_col;

    float acc_cv[4][4], acc_se[4][4];
    #pragma unroll
    for (int i = 0; i < 4; i++)
        #pragma unroll
        for (int j = 0; j < 4; j++) { acc_cv[i][j] = 0.f; acc_se[i][j] = 0.f; }

    // SE GEMM: K=64
    #pragma unroll
    for (int s = 0; s < 8; s++) {
        uint32_t fa0[4], fa1[4], fb[4];
        ldsm_x4(aAS + 32u * s, fa0);
        ldsm_x4(aAS + 16u * 272 + 32u * s, fa1);
        ldsm_x4(aBG + 32u * s, fb);
        mma_tf32(acc_se[0], fa0, fb[0], fb[1]);
        mma_tf32(acc_se[1], fa0, fb[2], fb[3]);
        mma_tf32(acc_se[2], fa1, fb[0], fb[1]);
        mma_tf32(acc_se[3], fa1, fb[2], fb[3]);
    }

    // conv GEMM: 3 passes x K=64
    #pragma unroll
    for (int pass = 0; pass < 3; pass++) {
        uint32_t abase = aAX + (uint32_t)pass * 272;
        uint32_t bbase = aBC + (uint32_t)pass * 256;
        #pragma unroll
        for (int s = 0; s < 8; s++) {
            uint32_t fa0[4], fa1[4], fb[4];
            ldsm_x4(abase + 32u * s, fa0);
            ldsm_x4(abase + 16u * 272 + 32u * s, fa1);
            ldsm_x4(bbase + 32u * s, fb);
            mma_tf32(acc_cv[0], fa0, fb[0], fb[1]);
            mma_tf32(acc_cv[1], fa0, fb[2], fb[3]);
            mma_tf32(acc_cv[2], fa1, fb[0], fb[1]);
            mma_tf32(acc_cv[3], fa1, fb[2], fb[3]);
        }
    }

    // epilogue: h = conv + ctx_b + relu(SE + seb), store tf32-rounded bits
    const int gr  = l >> 2;
    const int gc2 = (l & 3) * 2;
    #pragma unroll
    for (int mt = 0; mt < 2; mt++) {
        int row0 = w0 + R + mt * 16 + gr;
        float seb0 = __ldg(seW_b + row0);
        float seb1 = __ldg(seW_b + row0 + 8);
        #pragma unroll
        for (int nt = 0; nt < 2; nt++) {
            const float* cv = acc_cv[mt * 2 + nt];
            const float* se = acc_se[mt * 2 + nt];
            int col = Fo + nt * 8 + gc2;
            float cb0 = __ldg(ctx_b + col), cb1 = __ldg(ctx_b + col + 1);
            float* h0 = g_h + ((size_t)b * Wn + row0) * Fc + col;
            uint2 p0 = make_uint2(cvt_tf32(cv[0] + cb0 + fmaxf(se[0] + seb0, 0.f)),
                                  cvt_tf32(cv[1] + cb1 + fmaxf(se[1] + seb0, 0.f)));
            uint2 p1 = make_uint2(cvt_tf32(cv[2] + cb0 + fmaxf(se[2] + seb1, 0.f)),
                                  cvt_tf32(cv[3] + cb1 + fmaxf(se[3] + seb1, 0.f)));
            *(uint2*)(h0) = p0;
            *(uint2*)(h0 + 8 * Fc) = p1;
        }
    }
}

// ---------------------------------------------------------------------------
// Kernel O (mma.sync tf32): 128w x 128d tile per CTA, pure cp.async staging.
// ---------------------------------------------------------------------------
#define OM_A     0
#define OM_B     35360                    // 130*272 B
#define OM_SMEM  (OM_B + 128 * 784)       // 135712 B

__global__ void __launch_bounds__(512, 1) out_mma_kernel(float* __restrict__ out)
{
    extern __shared__ char smc[];
    uint32_t sbase = smem_u32(smc);
    const int t   = threadIdx.x;
    const int wid = t >> 5;
    const int l   = t & 31;
    const int b   = blockIdx.y;
    const int w0  = blockIdx.x * 128;

    const float* hb = g_h + (size_t)b * Wn * Fc;
    for (int i = t; i < 130 * 16; i += 512) {            // A: 2080 chunks
        int j = i >> 4, c4 = i & 15;
        int gw = (w0 - 1 + j + Wn) & (Wn - 1);
        cp_async16(sbase + OM_A + j * 272 + c4 * 16, hb + (size_t)gw * Fc + c4 * 4);
    }
    for (int i = t; i < 128 * 48; i += 512) {            // B: 6144 chunks
        int d = i / 48, c4 = i - d * 48;
        cp_async16(sbase + OM_B + d * 784 + c4 * 16, g_twB + d * 192 + c4 * 4);
    }
    cp_async_wait_all();
    __syncthreads();

    const int R = (wid & 3) * 32;
    const int D = (wid >> 2) * 32;

    const int a_row_in = (l & 7) + ((l >> 3) & 1) * 8;
    uint32_t aA = sbase + OM_A + (uint32_t)(R + a_row_in) * 272 + (uint32_t)(l >> 4) * 16;
    const int b_d_in = (l & 7) + (l >> 4) * 8;
    uint32_t aB = sbase + OM_B + (uint32_t)(D + b_d_in) * 784 + (uint32_t)((l >> 3) & 1) * 16;

    float acc[8][4];
    #pragma unroll
    for (int i = 0; i < 8; i++)
        #pragma unroll
        for (int j = 0; j < 4; j++) acc[i][j] = 0.f;

    #pragma unroll
    for (int pass = 0; pass < 3; pass++) {
        uint32_t a0base = aA + (uint32_t)pass * 272;
        uint32_t b0base = aB + (uint32_t)pass * 256;
        #pragma unroll
        for (int s = 0; s < 8; s++) {
            uint32_t fa0[4], fa1[4], fb0[4], fb1[4];
            ldsm_x4(a0base + 32u * s, fa0);
            ldsm_x4(a0base + 16u * 272 + 32u * s, fa1);
            ldsm_x4(b0base + 32u * s, fb0);
            ldsm_x4(b0base + 16u * 784 + 32u * s, fb1);
            mma_tf32(acc[0], fa0, fb0[0], fb0[1]);
            mma_tf32(acc[1], fa0, fb0[2], fb0[3]);
            mma_tf32(acc[2], fa0, fb1[0], fb1[1]);
            mma_tf32(acc[3], fa0, fb1[2], fb1[3]);
            mma_tf32(acc[4], fa1, fb0[0], fb0[1]);
            mma_tf32(acc[5], fa1, fb0[2], fb0[3]);
            mma_tf32(acc[6], fa1, fb1[0], fb1[1]);
            mma_tf32(acc[7], fa1, fb1[2], fb1[3]);
        }
    }

    const int gr  = l >> 2;
    const int gc2 = (l & 3) * 2;
    #pragma unroll
    for (int mt = 0; mt < 2; mt++) {
        #pragma unroll
        for (int nt = 0; nt < 4; nt++) {
            const float* c = acc[mt * 4 + nt];
            int w_row = w0 + R + mt * 16 + gr;
            int d_col = D + nt * 8 + gc2;
            float* ob = out + ((size_t)b * Wn + w_row) * Dc + d_col;
            *(float2*)(ob)          = make_float2(c[0], c[1]);
            *(float2*)(ob + 8 * Dc) = make_float2(c[2], c[3]);
        }
    }
}

// ---------------------------------------------------------------------------
extern "C" void kernel_launch(void* const* d_in, const int* in_sizes, int n_in,
                              void* d_out, int out_size) {
    const float* x       = (const float*)d_in[0];
    const float* ctx_w   = (const float*)d_in[1];
    const float* ctx_b   = (const float*)d_in[2];
    const float* token_w = (const float*)d_in[3];
    const float* seW_w   = (const float*)d_in[4];
    const float* seW_b   = (const float*)d_in[5];
    float* out = (float*)d_out;

    cudaFuncSetAttribute(h_mma_kernel,
                         cudaFuncAttributeMaxDynamicSharedMemorySize, HM_SMEM);
    cudaFuncSetAttribute(out_mma_kernel,
                         cudaFuncAttributeMaxDynamicSharedMemorySize, OM_SMEM);

    transpose_weights<<<96, 256>>>(ctx_w, token_w, seW_w);
    gram_partial<<<dim3(GRAM_CHUNKS, Bc), 256>>>(x);
    gram_reduce<<<Bc, 256>>>();
    h_mma_kernel<<<dim3(Wn / 128, Bc), 512, HM_SMEM>>>(x, ctx_b, seW_b);
    out_mma_kernel<<<dim3(Wn / 128, Bc), 512, OM_SMEM>>>(out);
}

// round 10
// speedup vs baseline: 1.9993x; 1.0509x over previous
#include <cuda_runtime.h>
#include <cstddef>
#include <cstdint>

#define Bc 48
#define Wn 8192
#define Fc 64
#define Dc 128
#define GRAM_CHUNKS 32

typedef unsigned long long ull;

// device scratch (no runtime allocation allowed). 16B-aligned.
__device__ __align__(16) float g_gram_part[Bc * GRAM_CHUNKS * Fc * Fc];
__device__ __align__(16) float g_gram[Bc * Fc * Fc];          // tf32-rounded
__device__ __align__(16) float g_h[(size_t)Bc * Wn * Fc];     // tf32-rounded
__device__ __align__(16) float g_xr[(size_t)Bc * Wn * Fc];    // tf32-rounded x
__device__ __align__(16) float g_cwB[64 * 192];               // [f][k*64+g], tf32
__device__ __align__(16) float g_twB[128 * 192];              // [d][k*64+f], tf32
__device__ __align__(16) float g_sewr[Wn * Fc];               // seW rounded tf32

// ---------------------------------------------------------------------------
// packed f32x2 helpers (gram)
// ---------------------------------------------------------------------------
__device__ __forceinline__ ull dup2(float a) {
    ull r;
    asm("mov.b64 %0, {%1, %1};" : "=l"(r) : "r"(__float_as_uint(a)));
    return r;
}
__device__ __forceinline__ void unpack2(ull v, float& a, float& b) {
    unsigned lo, hi;
    asm("mov.b64 {%0, %1}, %2;" : "=r"(lo), "=r"(hi) : "l"(v));
    a = __uint_as_float(lo); b = __uint_as_float(hi);
}
__device__ __forceinline__ ull ffma2(ull a, ull b, ull c) {
    ull d;
    asm("fma.rn.f32x2 %0, %1, %2, %3;" : "=l"(d) : "l"(a), "l"(b), "l"(c));
    return d;
}

// ---------------------------------------------------------------------------
// tensor-core / async helpers (legacy paths — compile under compute_103)
// ---------------------------------------------------------------------------
__device__ __forceinline__ uint32_t smem_u32(const void* p) {
    uint32_t a;
    asm("{ .reg .u64 t; cvta.to.shared.u64 t, %1; cvt.u32.u64 %0, t; }" : "=r"(a) : "l"(p));
    return a;
}
__device__ __forceinline__ uint32_t cvt_tf32(float x) {
    uint32_t r;
    asm("cvt.rna.tf32.f32 %0, %1;" : "=r"(r) : "f"(x));
    return r;
}
__device__ __forceinline__ void cp_async16(uint32_t saddr, const void* gptr) {
    asm volatile("cp.async.ca.shared.global [%0], [%1], 16;" :: "r"(saddr), "l"(gptr));
}
__device__ __forceinline__ void cp_commit() {
    asm volatile("cp.async.commit_group;");
}
__device__ __forceinline__ void cp_wait1() {
    asm volatile("cp.async.wait_group 1;" ::: "memory");
}
__device__ __forceinline__ void cp_wait0() {
    asm volatile("cp.async.wait_group 0;" ::: "memory");
}
__device__ __forceinline__ void ldsm_x4(uint32_t addr, uint32_t* r) {
    asm volatile("ldmatrix.sync.aligned.m8n8.x4.shared.b16 {%0,%1,%2,%3}, [%4];"
                 : "=r"(r[0]), "=r"(r[1]), "=r"(r[2]), "=r"(r[3]) : "r"(addr));
}
__device__ __forceinline__ void mma_tf32(float* c, const uint32_t* a,
                                         uint32_t b0, uint32_t b1) {
    asm volatile(
        "mma.sync.aligned.m16n8k8.row.col.f32.tf32.tf32.f32 "
        "{%0,%1,%2,%3}, {%4,%5,%6,%7}, {%8,%9}, {%0,%1,%2,%3};"
        : "+f"(c[0]), "+f"(c[1]), "+f"(c[2]), "+f"(c[3])
        : "r"(a[0]), "r"(a[1]), "r"(a[2]), "r"(a[3]), "r"(b0), "r"(b1));
}

// ---------------------------------------------------------------------------
// Kernel 0: weight reorders + pre-rounding of seW and x (prologue)
// ---------------------------------------------------------------------------
__global__ void __launch_bounds__(256) prep_kernel(
    const float* __restrict__ ctx_w, const float* __restrict__ token_w,
    const float* __restrict__ seW_w, const float* __restrict__ x) {
    int tid = blockIdx.x * 256 + threadIdx.x;
    int nt = gridDim.x * 256;
    for (int i = tid; i < 64 * 192; i += nt) {
        int f = i / 192, j = i - f * 192;
        int k = j >> 6, g = j & 63;
        g_cwB[i] = __uint_as_float(cvt_tf32(ctx_w[f * 192 + g * 3 + k]));
    }
    for (int i = tid; i < 128 * 192; i += nt) {
        int d = i / 192, j = i - d * 192;
        int k = j >> 6, f = j & 63;
        g_twB[i] = __uint_as_float(cvt_tf32(token_w[d * 192 + f * 3 + k]));
    }
    for (int i = tid; i < Wn * Fc / 4; i += nt) {
        float4 v = *((const float4*)seW_w + i);
        *((uint4*)g_sewr + i) =
            make_uint4(cvt_tf32(v.x), cvt_tf32(v.y), cvt_tf32(v.z), cvt_tf32(v.w));
    }
    for (size_t i = tid; i < (size_t)Bc * Wn * Fc / 4; i += nt) {
        float4 v = *((const float4*)x + i);
        *((uint4*)g_xr + i) =
            make_uint4(cvt_tf32(v.x), cvt_tf32(v.y), cvt_tf32(v.z), cvt_tf32(v.w));
    }
}

// ---------------------------------------------------------------------------
// Kernel 1: per-chunk partial Gram (FFMA2, float4 loads, parallel norm).
// ---------------------------------------------------------------------------
__global__ void __launch_bounds__(256) gram_partial(const float* __restrict__ x) {
    const int b = blockIdx.y;
    const int chunk = blockIdx.x;
    const int w_base = chunk * (Wn / GRAM_CHUNKS);

    __shared__ float xs[64][68];
    __shared__ float npart[4][64];
    __shared__ float sinv2[64];

    const int t = threadIdx.x;
    const int ti = t >> 4;
    const int tj = t & 15;

    ull acc[4][2];
    #pragma unroll
    for (int a = 0; a < 4; a++) { acc[a][0] = 0ull; acc[a][1] = 0ull; }

    const float* xb = x + (size_t)b * Wn * Fc;

    for (int tile = 0; tile < 256; tile += 64) {
        for (int i = t; i < 64 * 16; i += 256) {
            int r = i >> 4, c4 = i & 15;
            float4 v = *(const float4*)(xb + (size_t)(w_base + tile + r) * Fc + c4 * 4);
            *(float4*)(&xs[r][c4 * 4]) = v;
        }
        __syncthreads();
        {
            int q = t >> 6, r = t & 63;
            float s = 0.f;
            #pragma unroll
            for (int c = 0; c < 16; c++) { float v = xs[r][q * 16 + c]; s += v * v; }
            npart[q][r] = s;
        }
        __syncthreads();
        if (t < 64)
            sinv2[t] = 1.0f / (npart[0][t] + npart[1][t] + npart[2][t] + npart[3][t]);
        __syncthreads();

        #pragma unroll 4
        for (int w = 0; w < 64; w++) {
            float s = sinv2[w];
            const ull* row = (const ull*)(&xs[w][0]);
            ull vj0 = row[tj], vj1 = row[tj + 16];
            float vi0 = xs[w][ti] * s,      vi1 = xs[w][ti + 16] * s;
            float vi2 = xs[w][ti + 32] * s, vi3 = xs[w][ti + 48] * s;
            acc[0][0] = ffma2(dup2(vi0), vj0, acc[0][0]);
            acc[0][1] = ffma2(dup2(vi0), vj1, acc[0][1]);
            acc[1][0] = ffma2(dup2(vi1), vj0, acc[1][0]);
            acc[1][1] = ffma2(dup2(vi1), vj1, acc[1][1]);
            acc[2][0] = ffma2(dup2(vi2), vj0, acc[2][0]);
            acc[2][1] = ffma2(dup2(vi2), vj1, acc[2][1]);
            acc[3][0] = ffma2(dup2(vi3), vj0, acc[3][0]);
            acc[3][1] = ffma2(dup2(vi3), vj1, acc[3][1]);
        }
        __syncthreads();
    }

    float* dst = g_gram_part + ((size_t)b * GRAM_CHUNKS + chunk) * (Fc * Fc);
    #pragma unroll
    for (int a = 0; a < 4; a++)
        #pragma unroll
        for (int c = 0; c < 2; c++) {
            float u, v;
            unpack2(acc[a][c], u, v);
            *(float2*)(dst + (ti + 16 * a) * 64 + 2 * (tj + 16 * c)) = make_float2(u, v);
        }
}

__global__ void __launch_bounds__(256) gram_reduce() {
    const int b = blockIdx.x;
    const int t = threadIdx.x;
    for (int i = t; i < Fc * Fc; i += 256) {
        float s = 0.f;
        #pragma unroll
        for (int c = 0; c < GRAM_CHUNKS; c++)
            s += g_gram_part[((size_t)b * GRAM_CHUNKS + c) * (Fc * Fc) + i];
        g_gram[b * Fc * Fc + i] = __uint_as_float(cvt_tf32(s));
    }
}

// ---------------------------------------------------------------------------
// Kernel H (mma.sync tf32): 256w x 64f per CTA as two 128w sub-tiles.
// Pipelined cp.async: group0 = B + sub0 A, group1 = sub1 A.
// Merged accumulators: acc = relu(SE + seb) + ctx_b, then conv accumulates.
// ---------------------------------------------------------------------------
#define HM_AX   0                         // 258*272 = 70176 (stride 68 words)
#define HM_AS   70176                     // 256*272 = 69632
#define HM_BC   139808                    // 64*784  = 50176
#define HM_BG   189984                    // 64*272  = 17408
#define HM_SMEM 207392

__global__ void __launch_bounds__(512, 1) h_mma_kernel(
    const float* __restrict__ ctx_b,
    const float* __restrict__ seW_b)
{
    extern __shared__ char smc[];
    uint32_t sbase = smem_u32(smc);
    const int t   = threadIdx.x;
    const int wid = t >> 5;
    const int l   = t & 31;
    const int b   = blockIdx.y;
    const int w0  = blockIdx.x * 256;

    const float* xrb = g_xr + (size_t)b * Wn * Fc;

    // ---- group 0: B operands + sub0 A ----
    for (int i = t; i < 64 * 48; i += 512) {             // BC
        int f = i / 48, c4 = i - f * 48;
        cp_async16(sbase + HM_BC + f * 784 + c4 * 16, g_cwB + f * 192 + c4 * 4);
    }
    for (int i = t; i < 64 * 16; i += 512) {             // BG
        int f = i >> 4, c4 = i & 15;
        cp_async16(sbase + HM_BG + f * 272 + c4 * 16, g_gram + b * 4096 + f * 64 + c4 * 4);
    }
    for (int i = t; i < 128 * 16; i += 512) {            // AS rows 0..127
        int r = i >> 4, c4 = i & 15;
        cp_async16(sbase + HM_AS + r * 272 + c4 * 16,
                   g_sewr + (size_t)(w0 + r) * Fc + c4 * 4);
    }
    for (int i = t; i < 130 * 16; i += 512) {            // AX rows 0..129
        int j = i >> 4, c4 = i & 15;
        int gr = w0 - 1 + j;
        if (gr >= 0)
            cp_async16(sbase + HM_AX + j * 272 + c4 * 16, xrb + (size_t)gr * Fc + c4 * 4);
        else
            *(uint4*)(smc + HM_AX + j * 272 + c4 * 16) = make_uint4(0, 0, 0, 0);
    }
    cp_commit();
    // ---- group 1: sub1 A ----
    for (int i = t; i < 128 * 16; i += 512) {            // AS rows 128..255
        int r = 128 + (i >> 4), c4 = i & 15;
        cp_async16(sbase + HM_AS + r * 272 + c4 * 16,
                   g_sewr + (size_t)(w0 + r) * Fc + c4 * 4);
    }
    for (int i = t; i < 128 * 16; i += 512) {            // AX rows 130..257
        int j = 130 + (i >> 4), c4 = i & 15;
        int gr = w0 - 1 + j;
        if (gr < Wn)
            cp_async16(sbase + HM_AX + j * 272 + c4 * 16, xrb + (size_t)gr * Fc + c4 * 4);
        else
            *(uint4*)(smc + HM_AX + j * 272 + c4 * 16) = make_uint4(0, 0, 0, 0);
    }
    cp_commit();

    const int R  = (wid & 3) * 32;         // warp w-base within sub-tile
    const int Fo = (wid >> 2) * 16;        // warp f-base

    const int a_row_in = (l & 7) + ((l >> 3) & 1) * 8;
    const uint32_t a_col = (uint32_t)(l >> 4) * 16;
    const int b_row_in = (l & 7) + (l >> 4) * 8;
    const uint32_t b_col = (uint32_t)((l >> 3) & 1) * 16;
    uint32_t aBC = sbase + HM_BC + (uint32_t)(Fo + b_row_in) * 784 + b_col;
    uint32_t aBG = sbase + HM_BG + (uint32_t)(Fo + b_row_in) * 272 + b_col;

    const int gr  = l >> 2;
    const int gc2 = (l & 3) * 2;
    const int col = Fo + gc2;   // nt adds 8

    cp_wait1();
    __syncthreads();

    #pragma unroll
    for (int sub = 0; sub < 2; sub++) {
        if (sub == 1) { cp_wait0(); __syncthreads(); }

        uint32_t aAX = sbase + HM_AX + (uint32_t)(sub * 128 + R + a_row_in) * 272 + a_col;
        uint32_t aAS = sbase + HM_AS + (uint32_t)(sub * 128 + R + a_row_in) * 272 + a_col;

        float acc[4][4];
        #pragma unroll
        for (int i = 0; i < 4; i++)
            #pragma unroll
            for (int j = 0; j < 4; j++) acc[i][j] = 0.f;

        // SE GEMM: K=64
        #pragma unroll
        for (int s = 0; s < 8; s++) {
            uint32_t fa0[4], fa1[4], fb[4];
            ldsm_x4(aAS + 32u * s, fa0);
            ldsm_x4(aAS + 16u * 272 + 32u * s, fa1);
            ldsm_x4(aBG + 32u * s, fb);
            mma_tf32(acc[0], fa0, fb[0], fb[1]);
            mma_tf32(acc[1], fa0, fb[2], fb[3]);
            mma_tf32(acc[2], fa1, fb[0], fb[1]);
            mma_tf32(acc[3], fa1, fb[2], fb[3]);
        }

        // transform in place: acc = relu(acc + seb) + ctx_b
        {
            int row0 = w0 + sub * 128 + R + gr;
            float seb_a = __ldg(seW_b + row0);
            float seb_b = __ldg(seW_b + row0 + 8);
            float seb_c = __ldg(seW_b + row0 + 16);
            float seb_d = __ldg(seW_b + row0 + 24);
            float cb0a = __ldg(ctx_b + col),      cb1a = __ldg(ctx_b + col + 1);
            float cb0b = __ldg(ctx_b + col + 8),  cb1b = __ldg(ctx_b + col + 9);
            // acc[mt*2+nt]: rows (mt*16 + {0,8}), cols (nt*8 + {0,1})
            #pragma unroll
            for (int mt = 0; mt < 2; mt++) {
                float s0 = mt ? seb_c : seb_a;
                float s1 = mt ? seb_d : seb_b;
                #pragma unroll
                for (int nt = 0; nt < 2; nt++) {
                    float c0 = nt ? cb0b : cb0a;
                    float c1 = nt ? cb1b : cb1a;
                    float* a = acc[mt * 2 + nt];
                    a[0] = fmaxf(a[0] + s0, 0.f) + c0;
                    a[1] = fmaxf(a[1] + s0, 0.f) + c1;
                    a[2] = fmaxf(a[2] + s1, 0.f) + c0;
                    a[3] = fmaxf(a[3] + s1, 0.f) + c1;
                }
            }
        }

        // conv GEMM: 3 passes x K=64, accumulating onto transformed acc
        #pragma unroll
        for (int pass = 0; pass < 3; pass++) {
            uint32_t abase = aAX + (uint32_t)pass * 272;
            uint32_t bbase = aBC + (uint32_t)pass * 256;
            #pragma unroll
            for (int s = 0; s < 8; s++) {
                uint32_t fa0[4], fa1[4], fb[4];
                ldsm_x4(abase + 32u * s, fa0);
                ldsm_x4(abase + 16u * 272 + 32u * s, fa1);
                ldsm_x4(bbase + 32u * s, fb);
                mma_tf32(acc[0], fa0, fb[0], fb[1]);
                mma_tf32(acc[1], fa0, fb[2], fb[3]);
                mma_tf32(acc[2], fa1, fb[0], fb[1]);
                mma_tf32(acc[3], fa1, fb[2], fb[3]);
            }
        }

        // store h (tf32-rounded)
        #pragma unroll
        for (int mt = 0; mt < 2; mt++) {
            int row0 = w0 + sub * 128 + R + mt * 16 + gr;
            #pragma unroll
            for (int nt = 0; nt < 2; nt++) {
                const float* a = acc[mt * 2 + nt];
                float* h0 = g_h + ((size_t)b * Wn + row0) * Fc + col + nt * 8;
                *(uint2*)(h0) = make_uint2(cvt_tf32(a[0]), cvt_tf32(a[1]));
                *(uint2*)(h0 + 8 * Fc) = make_uint2(cvt_tf32(a[2]), cvt_tf32(a[3]));
            }
        }
    }
}

// ---------------------------------------------------------------------------
// Kernel O (mma.sync tf32): 256w x 128d per CTA as two 128w sub-tiles,
// pipelined cp.async staging.
// ---------------------------------------------------------------------------
#define OM_A     0                        // 258*272 = 70176
#define OM_B     70176                    // 128*784 = 100352
#define OM_SMEM  170528

__global__ void __launch_bounds__(512, 1) out_mma_kernel(float* __restrict__ out)
{
    extern __shared__ char smc[];
    uint32_t sbase = smem_u32(smc);
    const int t   = threadIdx.x;
    const int wid = t >> 5;
    const int l   = t & 31;
    const int b   = blockIdx.y;
    const int w0  = blockIdx.x * 256;

    const float* hb = g_h + (size_t)b * Wn * Fc;

    // group 0: B + A rows 0..129
    for (int i = t; i < 128 * 48; i += 512) {
        int d = i / 48, c4 = i - d * 48;
        cp_async16(sbase + OM_B + d * 784 + c4 * 16, g_twB + d * 192 + c4 * 4);
    }
    for (int i = t; i < 130 * 16; i += 512) {
        int j = i >> 4, c4 = i & 15;
        int gw = (w0 - 1 + j + Wn) & (Wn - 1);
        cp_async16(sbase + OM_A + j * 272 + c4 * 16, hb + (size_t)gw * Fc + c4 * 4);
    }
    cp_commit();
    // group 1: A rows 130..257
    for (int i = t; i < 128 * 16; i += 512) {
        int j = 130 + (i >> 4), c4 = i & 15;
        int gw = (w0 - 1 + j) & (Wn - 1);
        cp_async16(sbase + OM_A + j * 272 + c4 * 16, hb + (size_t)gw * Fc + c4 * 4);
    }
    cp_commit();

    const int R = (wid & 3) * 32;
    const int D = (wid >> 2) * 32;

    const int a_row_in = (l & 7) + ((l >> 3) & 1) * 8;
    const uint32_t a_col = (uint32_t)(l >> 4) * 16;
    const int b_d_in = (l & 7) + (l >> 4) * 8;
    uint32_t aB = sbase + OM_B + (uint32_t)(D + b_d_in) * 784 + (uint32_t)((l >> 3) & 1) * 16;

    const int gr  = l >> 2;
    const int gc2 = (l & 3) * 2;

    cp_wait1();
    __syncthreads();

    #pragma unroll
    for (int sub = 0; sub < 2; sub++) {
        if (sub == 1) { cp_wait0(); __syncthreads(); }

        uint32_t aA = sbase + OM_A + (uint32_t)(sub * 128 + R + a_row_in) * 272 + a_col;

        float acc[8][4];
        #pragma unroll
        for (int i = 0; i < 8; i++)
            #pragma unroll
            for (int j = 0; j < 4; j++) acc[i][j] = 0.f;

        #pragma unroll
        for (int pass = 0; pass < 3; pass++) {
            uint32_t a0base = aA + (uint32_t)pass * 272;
            uint32_t b0base = aB + (uint32_t)pass * 256;
            #pragma unroll
            for (int s = 0; s < 8; s++) {
                uint32_t fa0[4], fa1[4], fb0[4], fb1[4];
                ldsm_x4(a0base + 32u * s, fa0);
                ldsm_x4(a0base + 16u * 272 + 32u * s, fa1);
                ldsm_x4(b0base + 32u * s, fb0);
                ldsm_x4(b0base + 16u * 784 + 32u * s, fb1);
                mma_tf32(acc[0], fa0, fb0[0], fb0[1]);
                mma_tf32(acc[1], fa0, fb0[2], fb0[3]);
                mma_tf32(acc[2], fa0, fb1[0], fb1[1]);
                mma_tf32(acc[3], fa0, fb1[2], fb1[3]);
                mma_tf32(acc[4], fa1, fb0[0], fb0[1]);
                mma_tf32(acc[5], fa1, fb0[2], fb0[3]);
                mma_tf32(acc[6], fa1, fb1[0], fb1[1]);
                mma_tf32(acc[7], fa1, fb1[2], fb1[3]);
            }
        }

        #pragma unroll
        for (int mt = 0; mt < 2; mt++) {
            #pragma unroll
            for (int nt = 0; nt < 4; nt++) {
                const float* c = acc[mt * 4 + nt];
                int w_row = w0 + sub * 128 + R + mt * 16 + gr;
                int d_col = D + nt * 8 + gc2;
                float* ob = out + ((size_t)b * Wn + w_row) * Dc + d_col;
                *(float2*)(ob)          = make_float2(c[0], c[1]);
                *(float2*)(ob + 8 * Dc) = make_float2(c[2], c[3]);
            }
        }
    }
}

// ---------------------------------------------------------------------------
extern "C" void kernel_launch(void* const* d_in, const int* in_sizes, int n_in,
                              void* d_out, int out_size) {
    const float* x       = (const float*)d_in[0];
    const float* ctx_w   = (const float*)d_in[1];
    const float* ctx_b   = (const float*)d_in[2];
    const float* token_w = (const float*)d_in[3];
    const float* seW_w   = (const float*)d_in[4];
    const float* seW_b   = (const float*)d_in[5];
    float* out = (float*)d_out;

    cudaFuncSetAttribute(h_mma_kernel,
                         cudaFuncAttributeMaxDynamicSharedMemorySize, HM_SMEM);
    cudaFuncSetAttribute(out_mma_kernel,
                         cudaFuncAttributeMaxDynamicSharedMemorySize, OM_SMEM);

    prep_kernel<<<1024, 256>>>(ctx_w, token_w, seW_w, x);
    gram_partial<<<dim3(GRAM_CHUNKS, Bc), 256>>>(x);
    gram_reduce<<<Bc, 256>>>();
    h_mma_kernel<<<dim3(Wn / 256, Bc), 512, HM_SMEM>>>(ctx_b, seW_b);
    out_mma_kernel<<<dim3(Wn / 256, Bc), 512, OM_SMEM>>>(out);
}

// round 11
// speedup vs baseline: 2.1400x; 1.0704x over previous
#include <cuda_runtime.h>
#include <cstddef>
#include <cstdint>

#define Bc 48
#define Wn 8192
#define Fc 64
#define Dc 128
#define GRAM_CHUNKS 32

typedef unsigned long long ull;

// device scratch (no runtime allocation allowed). 16B-aligned.
__device__ __align__(16) float g_gram_part[Bc * GRAM_CHUNKS * Fc * Fc];
__device__ __align__(16) float g_gram[Bc * Fc * Fc];          // tf32-rounded
__device__ __align__(16) float g_h[(size_t)Bc * Wn * Fc];     // tf32-rounded
__device__ __align__(16) float g_xr[(size_t)Bc * Wn * Fc];    // tf32-rounded x
__device__ __align__(16) float g_cwB[64 * 192];               // [f][k*64+g], tf32
__device__ __align__(16) float g_twB[128 * 192];              // [d][k*64+f], tf32
__device__ __align__(16) float g_sewr[Wn * Fc];               // seW rounded tf32

// ---------------------------------------------------------------------------
// packed f32x2 helpers (gram)
// ---------------------------------------------------------------------------
__device__ __forceinline__ ull dup2(float a) {
    ull r;
    asm("mov.b64 %0, {%1, %1};" : "=l"(r) : "r"(__float_as_uint(a)));
    return r;
}
__device__ __forceinline__ void unpack2(ull v, float& a, float& b) {
    unsigned lo, hi;
    asm("mov.b64 {%0, %1}, %2;" : "=r"(lo), "=r"(hi) : "l"(v));
    a = __uint_as_float(lo); b = __uint_as_float(hi);
}
__device__ __forceinline__ ull ffma2(ull a, ull b, ull c) {
    ull d;
    asm("fma.rn.f32x2 %0, %1, %2, %3;" : "=l"(d) : "l"(a), "l"(b), "l"(c));
    return d;
}

// ---------------------------------------------------------------------------
// tensor-core / async helpers (legacy paths — compile under compute_103)
// ---------------------------------------------------------------------------
__device__ __forceinline__ uint32_t smem_u32(const void* p) {
    uint32_t a;
    asm("{ .reg .u64 t; cvta.to.shared.u64 t, %1; cvt.u32.u64 %0, t; }" : "=r"(a) : "l"(p));
    return a;
}
__device__ __forceinline__ uint32_t cvt_tf32(float x) {
    uint32_t r;
    asm("cvt.rna.tf32.f32 %0, %1;" : "=r"(r) : "f"(x));
    return r;
}
__device__ __forceinline__ void cp_async16(uint32_t saddr, const void* gptr) {
    asm volatile("cp.async.ca.shared.global [%0], [%1], 16;" :: "r"(saddr), "l"(gptr));
}
__device__ __forceinline__ void cp_commit() {
    asm volatile("cp.async.commit_group;");
}
__device__ __forceinline__ void cp_wait0() {
    asm volatile("cp.async.wait_group 0;" ::: "memory");
}
__device__ __forceinline__ void ldsm_x4(uint32_t addr, uint32_t* r) {
    asm volatile("ldmatrix.sync.aligned.m8n8.x4.shared.b16 {%0,%1,%2,%3}, [%4];"
                 : "=r"(r[0]), "=r"(r[1]), "=r"(r[2]), "=r"(r[3]) : "r"(addr));
}
__device__ __forceinline__ void mma_tf32(float* c, const uint32_t* a,
                                         uint32_t b0, uint32_t b1) {
    asm volatile(
        "mma.sync.aligned.m16n8k8.row.col.f32.tf32.tf32.f32 "
        "{%0,%1,%2,%3}, {%4,%5,%6,%7}, {%8,%9}, {%0,%1,%2,%3};"
        : "+f"(c[0]), "+f"(c[1]), "+f"(c[2]), "+f"(c[3])
        : "r"(a[0]), "r"(a[1]), "r"(a[2]), "r"(a[3]), "r"(b0), "r"(b1));
}

// ---------------------------------------------------------------------------
// Kernel 0: weight reorders + seW pre-rounding (small; x handled by gram_partial)
// ---------------------------------------------------------------------------
__global__ void __launch_bounds__(256) prep_kernel(
    const float* __restrict__ ctx_w, const float* __restrict__ token_w,
    const float* __restrict__ seW_w) {
    int tid = blockIdx.x * 256 + threadIdx.x;
    int nt = gridDim.x * 256;
    for (int i = tid; i < 64 * 192; i += nt) {
        int f = i / 192, j = i - f * 192;
        int k = j >> 6, g = j & 63;
        g_cwB[i] = __uint_as_float(cvt_tf32(ctx_w[f * 192 + g * 3 + k]));
    }
    for (int i = tid; i < 128 * 192; i += nt) {
        int d = i / 192, j = i - d * 192;
        int k = j >> 6, f = j & 63;
        g_twB[i] = __uint_as_float(cvt_tf32(token_w[d * 192 + f * 3 + k]));
    }
    for (int i = tid; i < Wn * Fc / 4; i += nt) {
        float4 v = *((const float4*)seW_w + i);
        *((uint4*)g_sewr + i) =
            make_uint4(cvt_tf32(v.x), cvt_tf32(v.y), cvt_tf32(v.z), cvt_tf32(v.w));
    }
}

// ---------------------------------------------------------------------------
// Kernel 1: per-chunk partial Gram + writes tf32-rounded x to g_xr.
// ---------------------------------------------------------------------------
__global__ void __launch_bounds__(256) gram_partial(const float* __restrict__ x) {
    const int b = blockIdx.y;
    const int chunk = blockIdx.x;
    const int w_base = chunk * (Wn / GRAM_CHUNKS);

    __shared__ float xs[64][68];
    __shared__ float npart[4][64];
    __shared__ float sinv2[64];

    const int t = threadIdx.x;
    const int ti = t >> 4;
    const int tj = t & 15;

    ull acc[4][2];
    #pragma unroll
    for (int a = 0; a < 4; a++) { acc[a][0] = 0ull; acc[a][1] = 0ull; }

    const float* xb = x + (size_t)b * Wn * Fc;
    float* xrb = g_xr + (size_t)b * Wn * Fc;

    for (int tile = 0; tile < 256; tile += 64) {
        for (int i = t; i < 64 * 16; i += 256) {
            int r = i >> 4, c4 = i & 15;
            size_t gofs = (size_t)(w_base + tile + r) * Fc + c4 * 4;
            float4 v = *(const float4*)(xb + gofs);
            *(float4*)(&xs[r][c4 * 4]) = v;
            // fold the tf32 pre-round of x here (x read exactly once grid-wide)
            *(uint4*)(xrb + gofs) =
                make_uint4(cvt_tf32(v.x), cvt_tf32(v.y), cvt_tf32(v.z), cvt_tf32(v.w));
        }
        __syncthreads();
        {
            int q = t >> 6, r = t & 63;
            float s = 0.f;
            #pragma unroll
            for (int c = 0; c < 16; c++) { float v = xs[r][q * 16 + c]; s += v * v; }
            npart[q][r] = s;
        }
        __syncthreads();
        if (t < 64)
            sinv2[t] = 1.0f / (npart[0][t] + npart[1][t] + npart[2][t] + npart[3][t]);
        __syncthreads();

        #pragma unroll 4
        for (int w = 0; w < 64; w++) {
            float s = sinv2[w];
            const ull* row = (const ull*)(&xs[w][0]);
            ull vj0 = row[tj], vj1 = row[tj + 16];
            float vi0 = xs[w][ti] * s,      vi1 = xs[w][ti + 16] * s;
            float vi2 = xs[w][ti + 32] * s, vi3 = xs[w][ti + 48] * s;
            acc[0][0] = ffma2(dup2(vi0), vj0, acc[0][0]);
            acc[0][1] = ffma2(dup2(vi0), vj1, acc[0][1]);
            acc[1][0] = ffma2(dup2(vi1), vj0, acc[1][0]);
            acc[1][1] = ffma2(dup2(vi1), vj1, acc[1][1]);
            acc[2][0] = ffma2(dup2(vi2), vj0, acc[2][0]);
            acc[2][1] = ffma2(dup2(vi2), vj1, acc[2][1]);
            acc[3][0] = ffma2(dup2(vi3), vj0, acc[3][0]);
            acc[3][1] = ffma2(dup2(vi3), vj1, acc[3][1]);
        }
        __syncthreads();
    }

    float* dst = g_gram_part + ((size_t)b * GRAM_CHUNKS + chunk) * (Fc * Fc);
    #pragma unroll
    for (int a = 0; a < 4; a++)
        #pragma unroll
        for (int c = 0; c < 2; c++) {
            float u, v;
            unpack2(acc[a][c], u, v);
            *(float2*)(dst + (ti + 16 * a) * 64 + 2 * (tj + 16 * c)) = make_float2(u, v);
        }
}

__global__ void __launch_bounds__(256) gram_reduce() {
    const int b = blockIdx.x;
    const int t = threadIdx.x;
    for (int i = t; i < Fc * Fc; i += 256) {
        float s = 0.f;
        #pragma unroll
        for (int c = 0; c < GRAM_CHUNKS; c++)
            s += g_gram_part[((size_t)b * GRAM_CHUNKS + c) * (Fc * Fc) + i];
        g_gram[b * Fc * Fc + i] = __uint_as_float(cvt_tf32(s));
    }
}

// ---------------------------------------------------------------------------
// Kernel H (mma.sync tf32): 256w x 64f per CTA, 16 warps = 8 wgroups(32w) x
// 2 fgroups(32f). acc = relu(SE + seb) + ctx_b, then conv accumulates.
// ---------------------------------------------------------------------------
#define HM_AX   0                         // 258*272 = 70176 (stride 68 words)
#define HM_AS   70176                     // 256*272 = 69632
#define HM_BC   139808                    // 64*784  = 50176
#define HM_BG   189984                    // 64*272  = 17408
#define HM_SMEM 207392

__global__ void __launch_bounds__(512, 1) h_mma_kernel(
    const float* __restrict__ ctx_b,
    const float* __restrict__ seW_b)
{
    extern __shared__ char smc[];
    uint32_t sbase = smem_u32(smc);
    const int t   = threadIdx.x;
    const int wid = t >> 5;
    const int l   = t & 31;
    const int b   = blockIdx.y;
    const int w0  = blockIdx.x * 256;

    const float* xrb = g_xr + (size_t)b * Wn * Fc;

    // ---- staging (one group) ----
    for (int i = t; i < 64 * 48; i += 512) {             // BC
        int f = i / 48, c4 = i - f * 48;
        cp_async16(sbase + HM_BC + f * 784 + c4 * 16, g_cwB + f * 192 + c4 * 4);
    }
    for (int i = t; i < 64 * 16; i += 512) {             // BG
        int f = i >> 4, c4 = i & 15;
        cp_async16(sbase + HM_BG + f * 272 + c4 * 16, g_gram + b * 4096 + f * 64 + c4 * 4);
    }
    for (int i = t; i < 256 * 16; i += 512) {            // AS rows 0..255
        int r = i >> 4, c4 = i & 15;
        cp_async16(sbase + HM_AS + r * 272 + c4 * 16,
                   g_sewr + (size_t)(w0 + r) * Fc + c4 * 4);
    }
    for (int i = t; i < 258 * 16; i += 512) {            // AX rows 0..257
        int j = i >> 4, c4 = i & 15;
        int gr = w0 - 1 + j;
        if (gr >= 0 && gr < Wn)
            cp_async16(sbase + HM_AX + j * 272 + c4 * 16, xrb + (size_t)gr * Fc + c4 * 4);
        else
            *(uint4*)(smc + HM_AX + j * 272 + c4 * 16) = make_uint4(0, 0, 0, 0);
    }
    cp_commit();

    const int fg = wid & 1;                // f0 = fg*32
    const int wg = wid >> 1;               // R = wg*32
    const int R  = wg * 32;
    const int f0 = fg * 32;

    const int a_row_in = (l & 7) + ((l >> 3) & 1) * 8;
    const uint32_t a_col = (uint32_t)(l >> 4) * 16;
    const int b_row_in = (l & 7) + (l >> 4) * 8;
    const uint32_t b_col = (uint32_t)((l >> 3) & 1) * 16;
    uint32_t aBC = sbase + HM_BC + (uint32_t)(f0 + b_row_in) * 784 + b_col;
    uint32_t aBG = sbase + HM_BG + (uint32_t)(f0 + b_row_in) * 272 + b_col;
    uint32_t aAX = sbase + HM_AX + (uint32_t)(R + a_row_in) * 272 + a_col;
    uint32_t aAS = sbase + HM_AS + (uint32_t)(R + a_row_in) * 272 + a_col;

    const int gr  = l >> 2;
    const int gc2 = (l & 3) * 2;

    float acc[2][4][4];                    // [m-tile][n-tile][frag]
    #pragma unroll
    for (int i = 0; i < 2; i++)
        #pragma unroll
        for (int j = 0; j < 4; j++)
            #pragma unroll
            for (int q = 0; q < 4; q++) acc[i][j][q] = 0.f;

    cp_wait0();
    __syncthreads();

    // ---- SE GEMM: K=64 ----
    #pragma unroll
    for (int s = 0; s < 8; s++) {
        uint32_t fa0[4], fa1[4], fb0[4], fb1[4];
        ldsm_x4(aAS + 32u * s, fa0);
        ldsm_x4(aAS + 16u * 272 + 32u * s, fa1);
        ldsm_x4(aBG + 32u * s, fb0);
        ldsm_x4(aBG + 16u * 272 + 32u * s, fb1);
        mma_tf32(acc[0][0], fa0, fb0[0], fb0[1]);
        mma_tf32(acc[0][1], fa0, fb0[2], fb0[3]);
        mma_tf32(acc[0][2], fa0, fb1[0], fb1[1]);
        mma_tf32(acc[0][3], fa0, fb1[2], fb1[3]);
        mma_tf32(acc[1][0], fa1, fb0[0], fb0[1]);
        mma_tf32(acc[1][1], fa1, fb0[2], fb0[3]);
        mma_tf32(acc[1][2], fa1, fb1[0], fb1[1]);
        mma_tf32(acc[1][3], fa1, fb1[2], fb1[3]);
    }

    // ---- transform in place: acc = relu(acc + seb) + ctx_b ----
    {
        int row0 = w0 + R + gr;
        float seb[4];
        seb[0] = __ldg(seW_b + row0);      // mt0, rows +0
        seb[1] = __ldg(seW_b + row0 + 8);  // mt0, rows +8
        seb[2] = __ldg(seW_b + row0 + 16); // mt1
        seb[3] = __ldg(seW_b + row0 + 24);
        #pragma unroll
        for (int mt = 0; mt < 2; mt++) {
            float s0 = seb[mt * 2], s1 = seb[mt * 2 + 1];
            #pragma unroll
            for (int ntile = 0; ntile < 4; ntile++) {
                int col = f0 + ntile * 8 + gc2;
                float c0 = __ldg(ctx_b + col), c1 = __ldg(ctx_b + col + 1);
                float* a = acc[mt][ntile];
                a[0] = fmaxf(a[0] + s0, 0.f) + c0;
                a[1] = fmaxf(a[1] + s0, 0.f) + c1;
                a[2] = fmaxf(a[2] + s1, 0.f) + c0;
                a[3] = fmaxf(a[3] + s1, 0.f) + c1;
            }
        }
    }

    // ---- conv GEMM: 3 passes x K=64, accumulating onto transformed acc ----
    #pragma unroll
    for (int pass = 0; pass < 3; pass++) {
        uint32_t abase = aAX + (uint32_t)pass * 272;
        uint32_t bbase = aBC + (uint32_t)pass * 256;
        #pragma unroll
        for (int s = 0; s < 8; s++) {
            uint32_t fa0[4], fa1[4], fb0[4], fb1[4];
            ldsm_x4(abase + 32u * s, fa0);
            ldsm_x4(abase + 16u * 272 + 32u * s, fa1);
            ldsm_x4(bbase + 32u * s, fb0);
            ldsm_x4(bbase + 16u * 784 + 32u * s, fb1);
            mma_tf32(acc[0][0], fa0, fb0[0], fb0[1]);
            mma_tf32(acc[0][1], fa0, fb0[2], fb0[3]);
            mma_tf32(acc[0][2], fa0, fb1[0], fb1[1]);
            mma_tf32(acc[0][3], fa0, fb1[2], fb1[3]);
            mma_tf32(acc[1][0], fa1, fb0[0], fb0[1]);
            mma_tf32(acc[1][1], fa1, fb0[2], fb0[3]);
            mma_tf32(acc[1][2], fa1, fb1[0], fb1[1]);
            mma_tf32(acc[1][3], fa1, fb1[2], fb1[3]);
        }
    }

    // ---- store h (tf32-rounded) ----
    #pragma unroll
    for (int mt = 0; mt < 2; mt++) {
        int row0 = w0 + R + mt * 16 + gr;
        #pragma unroll
        for (int ntile = 0; ntile < 4; ntile++) {
            const float* a = acc[mt][ntile];
            float* h0 = g_h + ((size_t)b * Wn + row0) * Fc + f0 + ntile * 8 + gc2;
            *(uint2*)(h0) = make_uint2(cvt_tf32(a[0]), cvt_tf32(a[1]));
            *(uint2*)(h0 + 8 * Fc) = make_uint2(cvt_tf32(a[2]), cvt_tf32(a[3]));
        }
    }
}

// ---------------------------------------------------------------------------
// Kernel O (mma.sync tf32): 256w x 128d per CTA, 16 warps = 4 wgroups(64w) x
// 4 dgroups(32d).
// ---------------------------------------------------------------------------
#define OM_A     0                        // 258*272 = 70176
#define OM_B     70176                    // 128*784 = 100352
#define OM_SMEM  170528

__global__ void __launch_bounds__(512, 1) out_mma_kernel(float* __restrict__ out)
{
    extern __shared__ char smc[];
    uint32_t sbase = smem_u32(smc);
    const int t   = threadIdx.x;
    const int wid = t >> 5;
    const int l   = t & 31;
    const int b   = blockIdx.y;
    const int w0  = blockIdx.x * 256;

    const float* hb = g_h + (size_t)b * Wn * Fc;

    for (int i = t; i < 128 * 48; i += 512) {
        int d = i / 48, c4 = i - d * 48;
        cp_async16(sbase + OM_B + d * 784 + c4 * 16, g_twB + d * 192 + c4 * 4);
    }
    for (int i = t; i < 258 * 16; i += 512) {
        int j = i >> 4, c4 = i & 15;
        int gw = (w0 - 1 + j + Wn) & (Wn - 1);
        cp_async16(sbase + OM_A + j * 272 + c4 * 16, hb + (size_t)gw * Fc + c4 * 4);
    }
    cp_commit();

    const int wg = wid & 3;                // R = wg*64
    const int dg = wid >> 2;               // D = dg*32
    const int R  = wg * 64;
    const int D  = dg * 32;

    const int a_row_in = (l & 7) + ((l >> 3) & 1) * 8;
    const uint32_t a_col = (uint32_t)(l >> 4) * 16;
    const int b_d_in = (l & 7) + (l >> 4) * 8;
    uint32_t aB = sbase + OM_B + (uint32_t)(D + b_d_in) * 784 + (uint32_t)((l >> 3) & 1) * 16;
    uint32_t aA = sbase + OM_A + (uint32_t)(R + a_row_in) * 272 + a_col;

    const int gr  = l >> 2;
    const int gc2 = (l & 3) * 2;

    float acc[4][4][4];                    // [m-tile][n-tile][frag]
    #pragma unroll
    for (int i = 0; i < 4; i++)
        #pragma unroll
        for (int j = 0; j < 4; j++)
            #pragma unroll
            for (int q = 0; q < 4; q++) acc[i][j][q] = 0.f;

    cp_wait0();
    __syncthreads();

    #pragma unroll
    for (int pass = 0; pass < 3; pass++) {
        uint32_t abase = aA + (uint32_t)pass * 272;
        uint32_t bbase = aB + (uint32_t)pass * 256;
        #pragma unroll
        for (int s = 0; s < 8; s++) {
            uint32_t fa[4][4], fb0[4], fb1[4];
            #pragma unroll
            for (int mt = 0; mt < 4; mt++)
                ldsm_x4(abase + (uint32_t)mt * 16u * 272 + 32u * s, fa[mt]);
            ldsm_x4(bbase + 32u * s, fb0);
            ldsm_x4(bbase + 16u * 784 + 32u * s, fb1);
            #pragma unroll
            for (int mt = 0; mt < 4; mt++) {
                mma_tf32(acc[mt][0], fa[mt], fb0[0], fb0[1]);
                mma_tf32(acc[mt][1], fa[mt], fb0[2], fb0[3]);
                mma_tf32(acc[mt][2], fa[mt], fb1[0], fb1[1]);
                mma_tf32(acc[mt][3], fa[mt], fb1[2], fb1[3]);
            }
        }
    }

    #pragma unroll
    for (int mt = 0; mt < 4; mt++) {
        #pragma unroll
        for (int ntile = 0; ntile < 4; ntile++) {
            const float* c = acc[mt][ntile];
            int w_row = w0 + R + mt * 16 + gr;
            int d_col = D + ntile * 8 + gc2;
            float* ob = out + ((size_t)b * Wn + w_row) * Dc + d_col;
            *(float2*)(ob)          = make_float2(c[0], c[1]);
            *(float2*)(ob + 8 * Dc) = make_float2(c[2], c[3]);
        }
    }
}

// ---------------------------------------------------------------------------
extern "C" void kernel_launch(void* const* d_in, const int* in_sizes, int n_in,
                              void* d_out, int out_size) {
    const float* x       = (const float*)d_in[0];
    const float* ctx_w   = (const float*)d_in[1];
    const float* ctx_b   = (const float*)d_in[2];
    const float* token_w = (const float*)d_in[3];
    const float* seW_w   = (const float*)d_in[4];
    const float* seW_b   = (const float*)d_in[5];
    float* out = (float*)d_out;

    cudaFuncSetAttribute(h_mma_kernel,
                         cudaFuncAttributeMaxDynamicSharedMemorySize, HM_SMEM);
    cudaFuncSetAttribute(out_mma_kernel,
                         cudaFuncAttributeMaxDynamicSharedMemorySize, OM_SMEM);

    gram_partial<<<dim3(GRAM_CHUNKS, Bc), 256>>>(x);
    prep_kernel<<<96, 256>>>(ctx_w, token_w, seW_w);
    gram_reduce<<<Bc, 256>>>();
    h_mma_kernel<<<dim3(Wn / 256, Bc), 512, HM_SMEM>>>(ctx_b, seW_b);
    out_mma_kernel<<<dim3(Wn / 256, Bc), 512, OM_SMEM>>>(out);
}

// round 12
// speedup vs baseline: 2.1991x; 1.0276x over previous
#include <cuda_runtime.h>
#include <cstddef>
#include <cstdint>

#define Bc 48
#define Wn 8192
#define Fc 64
#define Dc 128
#define GRAM_CHUNKS 32
#define WT 128                            // w rows per tile
#define NTILES ((Wn / WT) * Bc)           // 3072
#define NCTA 152

typedef unsigned long long ull;

// device scratch (no runtime allocation allowed). 16B-aligned.
__device__ __align__(16) float g_gram_part[Bc * GRAM_CHUNKS * Fc * Fc];
__device__ __align__(16) float g_gram[Bc * Fc * Fc];          // tf32-rounded
__device__ __align__(16) float g_h[(size_t)Bc * Wn * Fc];     // tf32-rounded
__device__ __align__(16) float g_xr[(size_t)Bc * Wn * Fc];    // tf32-rounded x
__device__ __align__(16) float g_cwB[64 * 192];               // [f][k*64+g], tf32
__device__ __align__(16) float g_twB[128 * 192];              // [d][k*64+f], tf32
__device__ __align__(16) float g_sewr[Wn * Fc];               // seW rounded tf32

// ---------------------------------------------------------------------------
// packed f32x2 helpers (gram)
// ---------------------------------------------------------------------------
__device__ __forceinline__ ull dup2(float a) {
    ull r;
    asm("mov.b64 %0, {%1, %1};" : "=l"(r) : "r"(__float_as_uint(a)));
    return r;
}
__device__ __forceinline__ void unpack2(ull v, float& a, float& b) {
    unsigned lo, hi;
    asm("mov.b64 {%0, %1}, %2;" : "=r"(lo), "=r"(hi) : "l"(v));
    a = __uint_as_float(lo); b = __uint_as_float(hi);
}
__device__ __forceinline__ ull ffma2(ull a, ull b, ull c) {
    ull d;
    asm("fma.rn.f32x2 %0, %1, %2, %3;" : "=l"(d) : "l"(a), "l"(b), "l"(c));
    return d;
}

// ---------------------------------------------------------------------------
// tensor-core / async helpers (legacy paths — compile under compute_103)
// ---------------------------------------------------------------------------
__device__ __forceinline__ uint32_t smem_u32(const void* p) {
    uint32_t a;
    asm("{ .reg .u64 t; cvta.to.shared.u64 t, %1; cvt.u32.u64 %0, t; }" : "=r"(a) : "l"(p));
    return a;
}
__device__ __forceinline__ uint32_t cvt_tf32(float x) {
    uint32_t r;
    asm("cvt.rna.tf32.f32 %0, %1;" : "=r"(r) : "f"(x));
    return r;
}
__device__ __forceinline__ void cp_async16(uint32_t saddr, const void* gptr) {
    asm volatile("cp.async.ca.shared.global [%0], [%1], 16;" :: "r"(saddr), "l"(gptr));
}
__device__ __forceinline__ void cp_commit() {
    asm volatile("cp.async.commit_group;");
}
__device__ __forceinline__ void cp_wait1() {
    asm volatile("cp.async.wait_group 1;" ::: "memory");
}
__device__ __forceinline__ void cp_wait0() {
    asm volatile("cp.async.wait_group 0;" ::: "memory");
}
__device__ __forceinline__ void ldsm_x4(uint32_t addr, uint32_t* r) {
    asm volatile("ldmatrix.sync.aligned.m8n8.x4.shared.b16 {%0,%1,%2,%3}, [%4];"
                 : "=r"(r[0]), "=r"(r[1]), "=r"(r[2]), "=r"(r[3]) : "r"(addr));
}
__device__ __forceinline__ void mma_tf32(float* c, const uint32_t* a,
                                         uint32_t b0, uint32_t b1) {
    asm volatile(
        "mma.sync.aligned.m16n8k8.row.col.f32.tf32.tf32.f32 "
        "{%0,%1,%2,%3}, {%4,%5,%6,%7}, {%8,%9}, {%0,%1,%2,%3};"
        : "+f"(c[0]), "+f"(c[1]), "+f"(c[2]), "+f"(c[3])
        : "r"(a[0]), "r"(a[1]), "r"(a[2]), "r"(a[3]), "r"(b0), "r"(b1));
}

// ---------------------------------------------------------------------------
// Kernel 0: weight reorders + seW pre-rounding
// ---------------------------------------------------------------------------
__global__ void __launch_bounds__(256) prep_kernel(
    const float* __restrict__ ctx_w, const float* __restrict__ token_w,
    const float* __restrict__ seW_w) {
    int tid = blockIdx.x * 256 + threadIdx.x;
    int nt = gridDim.x * 256;
    for (int i = tid; i < 64 * 192; i += nt) {
        int f = i / 192, j = i - f * 192;
        int k = j >> 6, g = j & 63;
        g_cwB[i] = __uint_as_float(cvt_tf32(ctx_w[f * 192 + g * 3 + k]));
    }
    for (int i = tid; i < 128 * 192; i += nt) {
        int d = i / 192, j = i - d * 192;
        int k = j >> 6, f = j & 63;
        g_twB[i] = __uint_as_float(cvt_tf32(token_w[d * 192 + f * 3 + k]));
    }
    for (int i = tid; i < Wn * Fc / 4; i += nt) {
        float4 v = *((const float4*)seW_w + i);
        *((uint4*)g_sewr + i) =
            make_uint4(cvt_tf32(v.x), cvt_tf32(v.y), cvt_tf32(v.z), cvt_tf32(v.w));
    }
}

// ---------------------------------------------------------------------------
// Kernel 1: per-chunk partial Gram + writes tf32-rounded x to g_xr.
// ---------------------------------------------------------------------------
__global__ void __launch_bounds__(256) gram_partial(const float* __restrict__ x) {
    const int b = blockIdx.y;
    const int chunk = blockIdx.x;
    const int w_base = chunk * (Wn / GRAM_CHUNKS);

    __shared__ float xs[64][68];
    __shared__ float npart[4][64];
    __shared__ float sinv2[64];

    const int t = threadIdx.x;
    const int ti = t >> 4;
    const int tj = t & 15;

    ull acc[4][2];
    #pragma unroll
    for (int a = 0; a < 4; a++) { acc[a][0] = 0ull; acc[a][1] = 0ull; }

    const float* xb = x + (size_t)b * Wn * Fc;
    float* xrb = g_xr + (size_t)b * Wn * Fc;

    for (int tile = 0; tile < 256; tile += 64) {
        for (int i = t; i < 64 * 16; i += 256) {
            int r = i >> 4, c4 = i & 15;
            size_t gofs = (size_t)(w_base + tile + r) * Fc + c4 * 4;
            float4 v = *(const float4*)(xb + gofs);
            *(float4*)(&xs[r][c4 * 4]) = v;
            *(uint4*)(xrb + gofs) =
                make_uint4(cvt_tf32(v.x), cvt_tf32(v.y), cvt_tf32(v.z), cvt_tf32(v.w));
        }
        __syncthreads();
        {
            int q = t >> 6, r = t & 63;
            float s = 0.f;
            #pragma unroll
            for (int c = 0; c < 16; c++) { float v = xs[r][q * 16 + c]; s += v * v; }
            npart[q][r] = s;
        }
        __syncthreads();
        if (t < 64)
            sinv2[t] = 1.0f / (npart[0][t] + npart[1][t] + npart[2][t] + npart[3][t]);
        __syncthreads();

        #pragma unroll 4
        for (int w = 0; w < 64; w++) {
            float s = sinv2[w];
            const ull* row = (const ull*)(&xs[w][0]);
            ull vj0 = row[tj], vj1 = row[tj + 16];
            float vi0 = xs[w][ti] * s,      vi1 = xs[w][ti + 16] * s;
            float vi2 = xs[w][ti + 32] * s, vi3 = xs[w][ti + 48] * s;
            acc[0][0] = ffma2(dup2(vi0), vj0, acc[0][0]);
            acc[0][1] = ffma2(dup2(vi0), vj1, acc[0][1]);
            acc[1][0] = ffma2(dup2(vi1), vj0, acc[1][0]);
            acc[1][1] = ffma2(dup2(vi1), vj1, acc[1][1]);
            acc[2][0] = ffma2(dup2(vi2), vj0, acc[2][0]);
            acc[2][1] = ffma2(dup2(vi2), vj1, acc[2][1]);
            acc[3][0] = ffma2(dup2(vi3), vj0, acc[3][0]);
            acc[3][1] = ffma2(dup2(vi3), vj1, acc[3][1]);
        }
        __syncthreads();
    }

    float* dst = g_gram_part + ((size_t)b * GRAM_CHUNKS + chunk) * (Fc * Fc);
    #pragma unroll
    for (int a = 0; a < 4; a++)
        #pragma unroll
        for (int c = 0; c < 2; c++) {
            float u, v;
            unpack2(acc[a][c], u, v);
            *(float2*)(dst + (ti + 16 * a) * 64 + 2 * (tj + 16 * c)) = make_float2(u, v);
        }
}

__global__ void __launch_bounds__(256) gram_reduce() {
    const int b = blockIdx.x;
    const int t = threadIdx.x;
    for (int i = t; i < Fc * Fc; i += 256) {
        float s = 0.f;
        #pragma unroll
        for (int c = 0; c < GRAM_CHUNKS; c++)
            s += g_gram_part[((size_t)b * GRAM_CHUNKS + c) * (Fc * Fc) + i];
        g_gram[b * Fc * Fc + i] = __uint_as_float(cvt_tf32(s));
    }
}

// ---------------------------------------------------------------------------
// Kernel H (persistent, mma.sync tf32): 128w x 64f tiles, double-buffered A.
// 256 threads = 8 warps: 4 wgroups(32w) x 2 fgroups(32f).
// BC staged once; per-tile: AX (x rows), AS (seW rows), BG (gram).
// ---------------------------------------------------------------------------
#define HM_BC    0                        // 64*784  = 50176
// buf 0: AX 50176 (35360), AS 85536 (34816), BG 120352 (17408)
// buf 1: AX 137760,        AS 173120,        BG 207936 -> end 225344
#define HM_SMEM  225344

__global__ void __launch_bounds__(256, 1) h_mma_kernel(
    const float* __restrict__ ctx_b,
    const float* __restrict__ seW_b)
{
    extern __shared__ char smc[];
    uint32_t sbase = smem_u32(smc);
    const int t   = threadIdx.x;
    const int wid = t >> 5;
    const int l   = t & 31;

    const uint32_t AXo[2] = {50176u, 137760u};
    const uint32_t ASo[2] = {85536u, 173120u};
    const uint32_t BGo[2] = {120352u, 207936u};

    // tile range for this CTA
    int per = NTILES / gridDim.x, rem = NTILES % gridDim.x;
    int cta = blockIdx.x;
    int start = cta * per + (cta < rem ? cta : rem);
    int cnt = per + (cta < rem ? 1 : 0);
    if (cnt == 0) return;

    // ---- stage BC (once) + tile `start` into buf 0, one group ----
    for (int i = t; i < 64 * 48; i += 256) {
        int f = i / 48, c4 = i - f * 48;
        cp_async16(sbase + HM_BC + f * 784 + c4 * 16, g_cwB + f * 192 + c4 * 4);
    }
    {
        int tau = start;
        int bb = tau >> 6, w0 = (tau & 63) * WT;
        const float* xrb = g_xr + (size_t)bb * Wn * Fc;
        for (int i = t; i < 130 * 16; i += 256) {
            int j = i >> 4, c4 = i & 15;
            int gr = w0 - 1 + j;
            if (gr >= 0 && gr < Wn)
                cp_async16(sbase + AXo[0] + j * 272 + c4 * 16, xrb + (size_t)gr * Fc + c4 * 4);
            else
                *(uint4*)(smc + AXo[0] + j * 272 + c4 * 16) = make_uint4(0, 0, 0, 0);
        }
        for (int i = t; i < 128 * 16; i += 256) {
            int r = i >> 4, c4 = i & 15;
            cp_async16(sbase + ASo[0] + r * 272 + c4 * 16,
                       g_sewr + (size_t)(w0 + r) * Fc + c4 * 4);
        }
        for (int i = t; i < 64 * 16; i += 256) {
            int f = i >> 4, c4 = i & 15;
            cp_async16(sbase + BGo[0] + f * 272 + c4 * 16,
                       g_gram + bb * 4096 + f * 64 + c4 * 4);
        }
    }
    cp_commit();

    // per-warp constants
    const int wg = wid >> 1;               // 0..3, R = wg*32
    const int fg = wid & 1;                // f0 = fg*32
    const int R  = wg * 32;
    const int f0 = fg * 32;
    const int a_row_in = (l & 7) + ((l >> 3) & 1) * 8;
    const uint32_t a_col = (uint32_t)(l >> 4) * 16;
    const int b_row_in = (l & 7) + (l >> 4) * 8;
    const uint32_t b_col = (uint32_t)((l >> 3) & 1) * 16;
    const uint32_t aBC = sbase + HM_BC + (uint32_t)(f0 + b_row_in) * 784 + b_col;
    const int gr  = l >> 2;
    const int gc2 = (l & 3) * 2;

    for (int it = 0; it < cnt; it++) {
        int buf = it & 1;
        // ---- prefetch next tile into other buffer ----
        if (it + 1 < cnt) {
            int tau = start + it + 1;
            int bb = tau >> 6, w0 = (tau & 63) * WT;
            int nb = buf ^ 1;
            const float* xrb = g_xr + (size_t)bb * Wn * Fc;
            for (int i = t; i < 130 * 16; i += 256) {
                int j = i >> 4, c4 = i & 15;
                int grr = w0 - 1 + j;
                if (grr >= 0 && grr < Wn)
                    cp_async16(sbase + AXo[nb] + j * 272 + c4 * 16,
                               xrb + (size_t)grr * Fc + c4 * 4);
                else
                    *(uint4*)(smc + AXo[nb] + j * 272 + c4 * 16) = make_uint4(0, 0, 0, 0);
            }
            for (int i = t; i < 128 * 16; i += 256) {
                int r = i >> 4, c4 = i & 15;
                cp_async16(sbase + ASo[nb] + r * 272 + c4 * 16,
                           g_sewr + (size_t)(w0 + r) * Fc + c4 * 4);
            }
            for (int i = t; i < 64 * 16; i += 256) {
                int f = i >> 4, c4 = i & 15;
                cp_async16(sbase + BGo[nb] + f * 272 + c4 * 16,
                           g_gram + bb * 4096 + f * 64 + c4 * 4);
            }
            cp_commit();
            cp_wait1();
        } else {
            cp_wait0();
        }
        __syncthreads();

        // ---- compute tile it from buf ----
        int tau = start + it;
        int bb = tau >> 6, w0 = (tau & 63) * WT;
        uint32_t aAX = sbase + AXo[buf] + (uint32_t)(R + a_row_in) * 272 + a_col;
        uint32_t aAS = sbase + ASo[buf] + (uint32_t)(R + a_row_in) * 272 + a_col;
        uint32_t aBG = sbase + BGo[buf] + (uint32_t)(f0 + b_row_in) * 272 + b_col;

        float acc[2][4][4];
        #pragma unroll
        for (int i = 0; i < 2; i++)
            #pragma unroll
            for (int j = 0; j < 4; j++)
                #pragma unroll
                for (int q = 0; q < 4; q++) acc[i][j][q] = 0.f;

        // SE GEMM: K=64
        #pragma unroll
        for (int s = 0; s < 8; s++) {
            uint32_t fa0[4], fa1[4], fb0[4], fb1[4];
            ldsm_x4(aAS + 32u * s, fa0);
            ldsm_x4(aAS + 16u * 272 + 32u * s, fa1);
            ldsm_x4(aBG + 32u * s, fb0);
            ldsm_x4(aBG + 16u * 272 + 32u * s, fb1);
            mma_tf32(acc[0][0], fa0, fb0[0], fb0[1]);
            mma_tf32(acc[0][1], fa0, fb0[2], fb0[3]);
            mma_tf32(acc[0][2], fa0, fb1[0], fb1[1]);
            mma_tf32(acc[0][3], fa0, fb1[2], fb1[3]);
            mma_tf32(acc[1][0], fa1, fb0[0], fb0[1]);
            mma_tf32(acc[1][1], fa1, fb0[2], fb0[3]);
            mma_tf32(acc[1][2], fa1, fb1[0], fb1[1]);
            mma_tf32(acc[1][3], fa1, fb1[2], fb1[3]);
        }

        // transform in place: acc = relu(acc + seb) + ctx_b
        {
            int row0 = w0 + R + gr;
            float seb0 = __ldg(seW_b + row0);
            float seb1 = __ldg(seW_b + row0 + 8);
            float seb2 = __ldg(seW_b + row0 + 16);
            float seb3 = __ldg(seW_b + row0 + 24);
            #pragma unroll
            for (int mt = 0; mt < 2; mt++) {
                float s0 = mt ? seb2 : seb0;
                float s1 = mt ? seb3 : seb1;
                #pragma unroll
                for (int ntile = 0; ntile < 4; ntile++) {
                    int col = f0 + ntile * 8 + gc2;
                    float c0 = __ldg(ctx_b + col), c1 = __ldg(ctx_b + col + 1);
                    float* a = acc[mt][ntile];
                    a[0] = fmaxf(a[0] + s0, 0.f) + c0;
                    a[1] = fmaxf(a[1] + s0, 0.f) + c1;
                    a[2] = fmaxf(a[2] + s1, 0.f) + c0;
                    a[3] = fmaxf(a[3] + s1, 0.f) + c1;
                }
            }
        }

        // conv GEMM: 3 passes x K=64
        #pragma unroll
        for (int pass = 0; pass < 3; pass++) {
            uint32_t abase = aAX + (uint32_t)pass * 272;
            uint32_t bbase = aBC + (uint32_t)pass * 256;
            #pragma unroll
            for (int s = 0; s < 8; s++) {
                uint32_t fa0[4], fa1[4], fb0[4], fb1[4];
                ldsm_x4(abase + 32u * s, fa0);
                ldsm_x4(abase + 16u * 272 + 32u * s, fa1);
                ldsm_x4(bbase + 32u * s, fb0);
                ldsm_x4(bbase + 16u * 784 + 32u * s, fb1);
                mma_tf32(acc[0][0], fa0, fb0[0], fb0[1]);
                mma_tf32(acc[0][1], fa0, fb0[2], fb0[3]);
                mma_tf32(acc[0][2], fa0, fb1[0], fb1[1]);
                mma_tf32(acc[0][3], fa0, fb1[2], fb1[3]);
                mma_tf32(acc[1][0], fa1, fb0[0], fb0[1]);
                mma_tf32(acc[1][1], fa1, fb0[2], fb0[3]);
                mma_tf32(acc[1][2], fa1, fb1[0], fb1[1]);
                mma_tf32(acc[1][3], fa1, fb1[2], fb1[3]);
            }
        }

        // store h (tf32-rounded)
        #pragma unroll
        for (int mt = 0; mt < 2; mt++) {
            int row0 = w0 + R + mt * 16 + gr;
            #pragma unroll
            for (int ntile = 0; ntile < 4; ntile++) {
                const float* a = acc[mt][ntile];
                float* h0 = g_h + ((size_t)bb * Wn + row0) * Fc + f0 + ntile * 8 + gc2;
                *(uint2*)(h0) = make_uint2(cvt_tf32(a[0]), cvt_tf32(a[1]));
                *(uint2*)(h0 + 8 * Fc) = make_uint2(cvt_tf32(a[2]), cvt_tf32(a[3]));
            }
        }
        __syncthreads();
    }
}

// ---------------------------------------------------------------------------
// Kernel O (persistent, mma.sync tf32): 128w x 128d tiles, double-buffered A.
// 256 threads = 8 warps: 2 wgroups(64w) x 4 dgroups(32d).
// B staged once; per-tile: A (h rows, circular).
// ---------------------------------------------------------------------------
#define OM_B     0                        // 128*784 = 100352
// buf 0: A 100352 (35360); buf 1: A 135712 -> end 171072
#define OM_SMEM  171072

__global__ void __launch_bounds__(256, 1) out_mma_kernel(float* __restrict__ out)
{
    extern __shared__ char smc[];
    uint32_t sbase = smem_u32(smc);
    const int t   = threadIdx.x;
    const int wid = t >> 5;
    const int l   = t & 31;

    const uint32_t Ao[2] = {100352u, 135712u};

    int per = NTILES / gridDim.x, rem = NTILES % gridDim.x;
    int cta = blockIdx.x;
    int start = cta * per + (cta < rem ? cta : rem);
    int cnt = per + (cta < rem ? 1 : 0);
    if (cnt == 0) return;

    // stage B (once) + tile `start` A into buf 0
    for (int i = t; i < 128 * 48; i += 256) {
        int d = i / 48, c4 = i - d * 48;
        cp_async16(sbase + OM_B + d * 784 + c4 * 16, g_twB + d * 192 + c4 * 4);
    }
    {
        int tau = start;
        int bb = tau >> 6, w0 = (tau & 63) * WT;
        const float* hb = g_h + (size_t)bb * Wn * Fc;
        for (int i = t; i < 130 * 16; i += 256) {
            int j = i >> 4, c4 = i & 15;
            int gw = (w0 - 1 + j + Wn) & (Wn - 1);
            cp_async16(sbase + Ao[0] + j * 272 + c4 * 16, hb + (size_t)gw * Fc + c4 * 4);
        }
    }
    cp_commit();

    const int wg = wid & 1;                // R = wg*64
    const int dg = wid >> 1;               // D = dg*32
    const int R  = wg * 64;
    const int D  = dg * 32;
    const int a_row_in = (l & 7) + ((l >> 3) & 1) * 8;
    const uint32_t a_col = (uint32_t)(l >> 4) * 16;
    const int b_d_in = (l & 7) + (l >> 4) * 8;
    const uint32_t aB = sbase + OM_B + (uint32_t)(D + b_d_in) * 784
                        + (uint32_t)((l >> 3) & 1) * 16;
    const int gr  = l >> 2;
    const int gc2 = (l & 3) * 2;

    for (int it = 0; it < cnt; it++) {
        int buf = it & 1;
        if (it + 1 < cnt) {
            int tau = start + it + 1;
            int bb = tau >> 6, w0 = (tau & 63) * WT;
            int nb = buf ^ 1;
            const float* hb = g_h + (size_t)bb * Wn * Fc;
            for (int i = t; i < 130 * 16; i += 256) {
                int j = i >> 4, c4 = i & 15;
                int gw = (w0 - 1 + j + Wn) & (Wn - 1);
                cp_async16(sbase + Ao[nb] + j * 272 + c4 * 16,
                           hb + (size_t)gw * Fc + c4 * 4);
            }
            cp_commit();
            cp_wait1();
        } else {
            cp_wait0();
        }
        __syncthreads();

        int tau = start + it;
        int bb = tau >> 6, w0 = (tau & 63) * WT;
        uint32_t aA = sbase + Ao[buf] + (uint32_t)(R + a_row_in) * 272 + a_col;

        float acc[4][4][4];
        #pragma unroll
        for (int i = 0; i < 4; i++)
            #pragma unroll
            for (int j = 0; j < 4; j++)
                #pragma unroll
                for (int q = 0; q < 4; q++) acc[i][j][q] = 0.f;

        #pragma unroll
        for (int pass = 0; pass < 3; pass++) {
            uint32_t abase = aA + (uint32_t)pass * 272;
            uint32_t bbase = aB + (uint32_t)pass * 256;
            #pragma unroll
            for (int s = 0; s < 8; s++) {
                uint32_t fa[4][4], fb0[4], fb1[4];
                #pragma unroll
                for (int mt = 0; mt < 4; mt++)
                    ldsm_x4(abase + (uint32_t)mt * 16u * 272 + 32u * s, fa[mt]);
                ldsm_x4(bbase + 32u * s, fb0);
                ldsm_x4(bbase + 16u * 784 + 32u * s, fb1);
                #pragma unroll
                for (int mt = 0; mt < 4; mt++) {
                    mma_tf32(acc[mt][0], fa[mt], fb0[0], fb0[1]);
                    mma_tf32(acc[mt][1], fa[mt], fb0[2], fb0[3]);
                    mma_tf32(acc[mt][2], fa[mt], fb1[0], fb1[1]);
                    mma_tf32(acc[mt][3], fa[mt], fb1[2], fb1[3]);
                }
            }
        }

        #pragma unroll
        for (int mt = 0; mt < 4; mt++) {
            #pragma unroll
            for (int ntile = 0; ntile < 4; ntile++) {
                const float* c = acc[mt][ntile];
                int w_row = w0 + R + mt * 16 + gr;
                int d_col = D + ntile * 8 + gc2;
                float* ob = out + ((size_t)bb * Wn + w_row) * Dc + d_col;
                *(float2*)(ob)          = make_float2(c[0], c[1]);
                *(float2*)(ob + 8 * Dc) = make_float2(c[2], c[3]);
            }
        }
        __syncthreads();
    }
}

// ---------------------------------------------------------------------------
extern "C" void kernel_launch(void* const* d_in, const int* in_sizes, int n_in,
                              void* d_out, int out_size) {
    const float* x       = (const float*)d_in[0];
    const float* ctx_w   = (const float*)d_in[1];
    const float* ctx_b   = (const float*)d_in[2];
    const float* token_w = (const float*)d_in[3];
    const float* seW_w   = (const float*)d_in[4];
    const float* seW_b   = (const float*)d_in[5];
    float* out = (float*)d_out;

    cudaFuncSetAttribute(h_mma_kernel,
                         cudaFuncAttributeMaxDynamicSharedMemorySize, HM_SMEM);
    cudaFuncSetAttribute(out_mma_kernel,
                         cudaFuncAttributeMaxDynamicSharedMemorySize, OM_SMEM);

    gram_partial<<<dim3(GRAM_CHUNKS, Bc), 256>>>(x);
    prep_kernel<<<96, 256>>>(ctx_w, token_w, seW_w);
    gram_reduce<<<Bc, 256>>>();
    h_mma_kernel<<<NCTA, 256, HM_SMEM>>>(ctx_b, seW_b);
    out_mma_kernel<<<NCTA, 256, OM_SMEM>>>(out);
}